// round 14
// baseline (speedup 1.0000x reference)
#include <cuda_runtime.h>
#include <cuda_bf16.h>
#include <cstdint>
#include <cstdio>

// ---------------- problem constants ----------------
#define BSZ    2
#define TT     16
#define LSEQ   3136          // TT * 196
#define NROW   6272          // BSZ * LSEQ (== 49*128)
#define DM     384
#define DI     768
#define DS     14
#define DTR    24
#define XCOLS  52            // DTR + 2*DS
#define XPAD   64            // xproj weight padded rows
#define DHID   1536          // 4*DM == 2*DI

// chunked scan
#define NC     56
#define CS     56

typedef __nv_bfloat16 bf16;

// weight arena offsets (elements)
#define WOFF_PATCH 0
#define WSZ_PATCH  (DM * DI)
#define WOFF_INW   (WOFF_PATCH + WSZ_PATCH)
#define WSZ_INW    (2 * DI * DM)
#define WOFF_OUTW  (WOFF_INW + 4 * WSZ_INW)
#define WSZ_OUTW   (DM * DI)
#define WOFF_FC1   (WOFF_OUTW + 4 * WSZ_OUTW)
#define WSZ_FC1    (DHID * DM)
#define WOFF_FC2   (WOFF_FC1 + 4 * WSZ_FC1)
#define WSZ_FC2    (DM * DHID)
#define WOFF_XPJ   (WOFF_FC2 + 4 * WSZ_FC2)
#define WSZ_XPJ    (XPAD * DI)                 // padded 64x768 per layer
#define WARENA     (WOFF_XPJ + 4 * WSZ_XPJ)

// ---------------- scratch ----------------
__device__ float g_xf [NROW * DI];
__device__ float g_h  [NROW * DM];
__device__ float2 g_stat[NROW];               // per-row (mu, rsqrt)
__device__ float g_xz [NROW * 2 * DI];
__device__ float g_xc [NROW * DI];
__device__ float g_dbl[NROW * XCOLS];
__device__ float g_dt [NROW * DI];
__device__ float g_y  [NROW * DI];
__device__ float g_m1 [NROW * DHID];
__device__ float g_P  [BSZ * NC * DI * DS];
__device__ float g_S  [BSZ * NC * DI * DS];
__device__ float g_h0 [BSZ * NC * DI * DS];
// persistent hi/lo weight arena (all layers)
__device__ __align__(16) bf16 g_wh[WARENA];
__device__ __align__(16) bf16 g_wl[WARENA];

// ---------------- activations ----------------
__device__ __forceinline__ float softplus_f(float x) {
    return fmaxf(x, 0.f) + log1pf(expf(-fabsf(x)));
}
__device__ __forceinline__ float gelu_f(float x) {
    float x3 = x * x * x;
    float t = tanhf(0.7978845608028654f * (x + 0.044715f * x3));
    return 0.5f * x * (1.f + t);
}

__device__ __forceinline__ uint32_t smem_u32(const void* p) {
    uint32_t a;
    asm("{ .reg .u64 t; cvta.to.shared.u64 t, %1; cvt.u32.u64 %0, t; }" : "=r"(a) : "l"(p));
    return a;
}

__device__ __forceinline__ void split_bf16(float v, bf16& hi, bf16& lo) {
    hi = __float2bfloat16(v);
    lo = __float2bfloat16(v - __bfloat162float(hi));
}

// ================= bf16-split tensor-core GEMM (mma.sync) =================
// C[M,N] = act(A[M,K]*W^T + bias) + res.  A fp32 (split in-kernel);
// optional row-wise layernorm fused into the A load (lnStat/lnG/lnB).
// W pre-split bf16 hi/lo from the arena.  M%128==0, N%64==0, K%32==0.
// Warp tile 32x32 (8 warps as 4x2).
#define KB 32
#define SROW 40
#define MG_AH 0
#define MG_AL 10240
#define MG_WH 20480
#define MG_WL 25600
#define MG_STAGE 30720
#define MG_SMEM (2 * MG_STAGE)

__device__ __forceinline__ void ldm_x4(uint32_t& r0, uint32_t& r1, uint32_t& r2,
                                       uint32_t& r3, uint32_t addr) {
    asm volatile("ldmatrix.sync.aligned.m8n8.x4.shared.b16 {%0,%1,%2,%3}, [%4];"
                 : "=r"(r0), "=r"(r1), "=r"(r2), "=r"(r3) : "r"(addr));
}
__device__ __forceinline__ void mma_bf16(float* d, const uint32_t* a,
                                         uint32_t b0, uint32_t b1) {
    asm volatile(
        "mma.sync.aligned.m16n8k16.row.col.f32.bf16.bf16.f32 "
        "{%0,%1,%2,%3}, {%4,%5,%6,%7}, {%8,%9}, {%0,%1,%2,%3};"
        : "+f"(d[0]), "+f"(d[1]), "+f"(d[2]), "+f"(d[3])
        : "r"(a[0]), "r"(a[1]), "r"(a[2]), "r"(a[3]), "r"(b0), "r"(b1));
}

__device__ __forceinline__ void cvt_split4(float4 v, uint16_t* hi, uint16_t* lo) {
    __nv_bfloat16 hx = __float2bfloat16(v.x), hy = __float2bfloat16(v.y);
    __nv_bfloat16 hz = __float2bfloat16(v.z), hw = __float2bfloat16(v.w);
    __nv_bfloat16 gx = __float2bfloat16(v.x - __bfloat162float(hx));
    __nv_bfloat16 gy = __float2bfloat16(v.y - __bfloat162float(hy));
    __nv_bfloat16 gz = __float2bfloat16(v.z - __bfloat162float(hz));
    __nv_bfloat16 gw = __float2bfloat16(v.w - __bfloat162float(hw));
    uint2 hp, lp;
    hp.x = (uint32_t)__bfloat16_as_ushort(hy) << 16 | __bfloat16_as_ushort(hx);
    hp.y = (uint32_t)__bfloat16_as_ushort(hw) << 16 | __bfloat16_as_ushort(hz);
    lp.x = (uint32_t)__bfloat16_as_ushort(gy) << 16 | __bfloat16_as_ushort(gx);
    lp.y = (uint32_t)__bfloat16_as_ushort(gw) << 16 | __bfloat16_as_ushort(gz);
    *(uint2*)hi = hp;
    *(uint2*)lo = lp;
}

// apply layernorm to a float4 of row elements at columns col..col+3
__device__ __forceinline__ void apply_ln4(float4& v, float mu, float r,
                                          const float* g, const float* b, int col) {
    float4 gv = *(const float4*)(g + col);
    float4 bv = *(const float4*)(b + col);
    float cx = r * gv.x, cy = r * gv.y, cz = r * gv.z, cw = r * gv.w;
    v.x = fmaf(v.x, cx, fmaf(-mu, cx, bv.x));
    v.y = fmaf(v.y, cy, fmaf(-mu, cy, bv.y));
    v.z = fmaf(v.z, cz, fmaf(-mu, cz, bv.z));
    v.w = fmaf(v.w, cw, fmaf(-mu, cw, bv.w));
}

__global__ __launch_bounds__(256, 2) void mma_gemm(
    const float* __restrict__ A, int lda,
    const bf16* __restrict__ Wh, const bf16* __restrict__ Wl, int ldw,
    float* __restrict__ C, int ldc,
    const float* __restrict__ bias,
    const float* __restrict__ res,
    int K, int act, int nReal,
    const float2* __restrict__ lnStat,
    const float* __restrict__ lnG,
    const float* __restrict__ lnB)
{
    extern __shared__ __align__(16) char dsm[];

    int tid  = threadIdx.x;
    int wid  = tid >> 5;
    int lane = tid & 31;
    int bm0 = blockIdx.y * 128;
    int bn0 = blockIdx.x * 64;
    int wm = (wid >> 1) * 32;   // 0/32/64/96
    int wn = (wid & 1) * 32;    // 0/32

    float acc[2][4][4];
#pragma unroll
    for (int mt = 0; mt < 2; mt++)
#pragma unroll
        for (int nt = 0; nt < 4; nt++)
#pragma unroll
            for (int i = 0; i < 4; i++) acc[mt][nt][i] = 0.f;

    int lrA[4], lcA[4];
#pragma unroll
    for (int i = 0; i < 4; i++) {
        int idx = i * 256 + tid;
        lrA[i] = idx >> 3;
        lcA[i] = (idx & 7) * 4;
    }
    int wr = tid >> 2, wc = (tid & 3) * 8;
    uint32_t oW = (uint32_t)(wr * SROW + wc) * 2;

    const bf16* gWh = Wh + (size_t)(bn0 + wr) * ldw + wc;
    const bf16* gWl = Wl + (size_t)(bn0 + wr) * ldw + wc;

    // per-slot row LN stats (fixed across chunks)
    float2 st[4];
    if (lnStat) {
#pragma unroll
        for (int i = 0; i < 4; i++) st[i] = lnStat[bm0 + lrA[i]];
    }

    float4 pa[4];
    uint4 pwh, pwl;
#pragma unroll
    for (int i = 0; i < 4; i++)
        pa[i] = *(const float4*)(A + (size_t)(bm0 + lrA[i]) * lda + lcA[i]);
    pwh = *(const uint4*)gWh;
    pwl = *(const uint4*)gWl;

    {
        char* sn = dsm;
#pragma unroll
        for (int i = 0; i < 4; i++) {
            if (lnStat) apply_ln4(pa[i], st[i].x, st[i].y, lnG, lnB, lcA[i]);
            int o = lrA[i] * SROW + lcA[i];
            cvt_split4(pa[i], (uint16_t*)(sn + MG_AH) + o, (uint16_t*)(sn + MG_AL) + o);
        }
        *(uint4*)(sn + MG_WH + oW) = pwh;
        *(uint4*)(sn + MG_WL + oW) = pwl;
    }
    __syncthreads();

    uint32_t sAh[2], sAl[2], sWh[2], sWl[2];
#pragma unroll
    for (int s = 0; s < 2; s++) {
        sAh[s] = smem_u32(dsm + s * MG_STAGE + MG_AH);
        sAl[s] = smem_u32(dsm + s * MG_STAGE + MG_AL);
        sWh[s] = smem_u32(dsm + s * MG_STAGE + MG_WH);
        sWl[s] = smem_u32(dsm + s * MG_STAGE + MG_WL);
    }

    int frow = lane & 15;
    int fk   = (lane >> 4) << 3;

    int nch = K / KB;
    for (int c = 0; c < nch; c++) {
        int cur = c & 1, nxt = cur ^ 1;
        int ko = (c + 1) * KB;

        if (c + 1 < nch) {
#pragma unroll
            for (int i = 0; i < 4; i++)
                pa[i] = *(const float4*)(A + (size_t)(bm0 + lrA[i]) * lda + ko + lcA[i]);
            pwh = *(const uint4*)(gWh + ko);
            pwl = *(const uint4*)(gWl + ko);
        }

#pragma unroll
        for (int k0 = 0; k0 < KB; k0 += 16) {
            // W fragments: 32 cols of this warp, hi and lo (4 ldmatrix)
            uint32_t bh[4][2], bl[4][2];
#pragma unroll
            for (int nh = 0; nh < 2; nh++) {
                uint32_t off = (uint32_t)((wn + nh * 16 + frow) * SROW + k0 + fk) * 2;
                uint32_t r0, r1, r2, r3;
                ldm_x4(r0, r1, r2, r3, sWh[cur] + off);
                bh[nh * 2 + 0][0] = r0; bh[nh * 2 + 0][1] = r2;
                bh[nh * 2 + 1][0] = r1; bh[nh * 2 + 1][1] = r3;
                ldm_x4(r0, r1, r2, r3, sWl[cur] + off);
                bl[nh * 2 + 0][0] = r0; bl[nh * 2 + 0][1] = r2;
                bl[nh * 2 + 1][0] = r1; bl[nh * 2 + 1][1] = r3;
            }
            // A fragments: 32 rows, hi and lo (4 ldmatrix), then 24 MMA
#pragma unroll
            for (int mt = 0; mt < 2; mt++) {
                uint32_t off = (uint32_t)((wm + mt * 16 + frow) * SROW + k0 + fk) * 2;
                uint32_t ah[4], al[4];
                ldm_x4(ah[0], ah[1], ah[2], ah[3], sAh[cur] + off);
                ldm_x4(al[0], al[1], al[2], al[3], sAl[cur] + off);
#pragma unroll
                for (int nt = 0; nt < 4; nt++) {
                    mma_bf16(acc[mt][nt], ah, bh[nt][0], bh[nt][1]);
                    mma_bf16(acc[mt][nt], ah, bl[nt][0], bl[nt][1]);
                    mma_bf16(acc[mt][nt], al, bh[nt][0], bh[nt][1]);
                }
            }
        }

        if (c + 1 < nch) {
            char* sn = dsm + nxt * MG_STAGE;
#pragma unroll
            for (int i = 0; i < 4; i++) {
                if (lnStat) apply_ln4(pa[i], st[i].x, st[i].y, lnG, lnB, ko + lcA[i]);
                int o = lrA[i] * SROW + lcA[i];
                cvt_split4(pa[i], (uint16_t*)(sn + MG_AH) + o, (uint16_t*)(sn + MG_AL) + o);
            }
            *(uint4*)(sn + MG_WH + oW) = pwh;
            *(uint4*)(sn + MG_WL + oW) = pwl;
            __syncthreads();
        }
    }

    // epilogue: fragment row = lane/4 (+8), col = (lane%4)*2 (+1)
    int gq = lane >> 2;
    int gr = (lane & 3) * 2;
#pragma unroll
    for (int mt = 0; mt < 2; mt++) {
#pragma unroll
        for (int half = 0; half < 2; half++) {
            int gm = bm0 + wm + mt * 16 + gq + half * 8;
            float* crow = C + (size_t)gm * ldc;
            const float* rrow = res ? res + (size_t)gm * ldc : nullptr;
#pragma unroll
            for (int nt = 0; nt < 4; nt++) {
                int gn = bn0 + wn + nt * 8 + gr;
                if (gn >= nReal) continue;
                float v0 = acc[mt][nt][half * 2 + 0];
                float v1 = acc[mt][nt][half * 2 + 1];
                if (bias) { v0 += bias[gn]; v1 += bias[gn + 1]; }
                if (act == 2)      { v0 = gelu_f(v0);     v1 = gelu_f(v1); }
                else if (act == 1) { v0 = softplus_f(v0); v1 = softplus_f(v1); }
                if (rrow) { v0 += rrow[gn]; v1 += rrow[gn + 1]; }
                *(float2*)(crow + gn) = make_float2(v0, v1);
            }
        }
    }
}

// ---------------- row stats for fused layernorm ----------------
__global__ void rowstat_k(const float* __restrict__ x, float2* __restrict__ stat)
{
    int row = blockIdx.x;
    int t = threadIdx.x;
    const float* xr = x + (size_t)row * DM;
    float v0 = xr[t], v1 = xr[t + 128], v2 = xr[t + 256];
    float s  = v0 + v1 + v2;
    float s2 = v0 * v0 + v1 * v1 + v2 * v2;
#pragma unroll
    for (int o = 16; o; o >>= 1) {
        s  += __shfl_xor_sync(0xffffffffu, s,  o);
        s2 += __shfl_xor_sync(0xffffffffu, s2, o);
    }
    __shared__ float ss[4], ss2[4];
    int w = t >> 5;
    if ((t & 31) == 0) { ss[w] = s; ss2[w] = s2; }
    __syncthreads();
    if (t == 0) {
        s  = ss[0] + ss[1] + ss[2] + ss[3];
        s2 = ss2[0] + ss2[1] + ss2[2] + ss2[3];
        float mu  = s * (1.f / DM);
        float var = s2 * (1.f / DM) - mu * mu;
        stat[row] = make_float2(mu, rsqrtf(var + 1e-5f));
    }
}

// ---------------- weight fp32 -> bf16 hi/lo (grid-strided) ----------------
__global__ void wcvt_k(const float* __restrict__ w, bf16* __restrict__ hi,
                       bf16* __restrict__ lo, int n) {
    for (int i = blockIdx.x * 256 + threadIdx.x; i < n; i += gridDim.x * 256) {
        bf16 h, l;
        split_bf16(w[i], h, l);
        hi[i] = h; lo[i] = l;
    }
}

// xproj weights: pad 52 rows -> 64 rows (zeros), all 4 layers in one launch
__global__ void wcvt_xpj_k(const float* __restrict__ w, bf16* __restrict__ hi,
                           bf16* __restrict__ lo) {
    int i = blockIdx.x * 256 + threadIdx.x;
    if (i >= 4 * XPAD * DI) return;
    int layer = i / (XPAD * DI);
    int rem = i % (XPAD * DI);
    int row = rem / DI;
    int col = rem % DI;
    float v = (row < XCOLS) ? w[((size_t)layer * XCOLS + row) * DI + col] : 0.f;
    bf16 h, l;
    split_bf16(v, h, l);
    hi[i] = h; lo[i] = l;
}

// ---------------- patchify gather ----------------
__global__ void gather_patches_k(const float* __restrict__ x, float* __restrict__ xf) {
    int idx = blockIdx.x * blockDim.x + threadIdx.x;
    if (idx >= NROW * DI) return;
    int c   = idx % DI;
    int row = idx / DI;
    int n  = row / 196, p = row % 196;
    int ph = p / 14,   pw = p % 14;
    int ch = c >> 8;
    int rem = c & 255;
    int py = rem >> 4, px = rem & 15;
    xf[idx] = x[((size_t)(n * 3 + ch) * 224 + (ph * 16 + py)) * 224 + (pw * 16 + px)];
}

// ================= FFMA 128x128 double-buffered SGEMM (K%8==0, for dt) ===========
#define TBM 128
#define TBN 128
#define TBK 8
__global__ __launch_bounds__(256, 2) void sgemm128(
    const float* __restrict__ A, int lda,
    const float* __restrict__ W, int ldw,
    float* __restrict__ C, int ldc,
    const float* __restrict__ bias,
    const float* __restrict__ res,
    int N, int K, int act)
{
    __shared__ __align__(16) float As[2][TBK][TBM];
    __shared__ __align__(16) float Ws[2][TBK][TBN];

    int bm0 = blockIdx.y * TBM;
    int bn0 = blockIdx.x * TBN;
    int tid = threadIdx.x;
    int tm = tid >> 4;
    int tn = tid & 15;
    int lr = tid >> 1;
    int lk = (tid & 1) * 4;

    const float* Aptr = A + (size_t)(bm0 + lr) * lda + lk;
    bool wok = (bn0 + lr) < N;
    const float* Wptr = W + (size_t)(wok ? (bn0 + lr) : 0) * ldw + lk;

    float4 av = *(const float4*)Aptr;
    float4 wv = wok ? *(const float4*)Wptr : make_float4(0.f, 0.f, 0.f, 0.f);
    As[0][lk + 0][lr] = av.x; As[0][lk + 1][lr] = av.y;
    As[0][lk + 2][lr] = av.z; As[0][lk + 3][lr] = av.w;
    Ws[0][lk + 0][lr] = wv.x; Ws[0][lk + 1][lr] = wv.y;
    Ws[0][lk + 2][lr] = wv.z; Ws[0][lk + 3][lr] = wv.w;
    __syncthreads();

    float acc[8][8];
#pragma unroll
    for (int i = 0; i < 8; i++)
#pragma unroll
        for (int j = 0; j < 8; j++) acc[i][j] = 0.f;

    int nk = K / TBK;
    for (int kt = 0; kt < nk; kt++) {
        int cur = kt & 1, nxt = cur ^ 1;
        if (kt + 1 < nk) {
            av = *(const float4*)(Aptr + (size_t)(kt + 1) * TBK);
            wv = wok ? *(const float4*)(Wptr + (size_t)(kt + 1) * TBK)
                     : make_float4(0.f, 0.f, 0.f, 0.f);
        }
#pragma unroll
        for (int kk = 0; kk < TBK; kk++) {
            float4 a0 = *(const float4*)&As[cur][kk][tm * 4];
            float4 a1 = *(const float4*)&As[cur][kk][tm * 4 + 64];
            float4 w0 = *(const float4*)&Ws[cur][kk][tn * 4];
            float4 w1 = *(const float4*)&Ws[cur][kk][tn * 4 + 64];
            float a[8] = {a0.x, a0.y, a0.z, a0.w, a1.x, a1.y, a1.z, a1.w};
            float w[8] = {w0.x, w0.y, w0.z, w0.w, w1.x, w1.y, w1.z, w1.w};
#pragma unroll
            for (int i = 0; i < 8; i++)
#pragma unroll
                for (int j = 0; j < 8; j++)
                    acc[i][j] = fmaf(a[i], w[j], acc[i][j]);
        }
        if (kt + 1 < nk) {
            As[nxt][lk + 0][lr] = av.x; As[nxt][lk + 1][lr] = av.y;
            As[nxt][lk + 2][lr] = av.z; As[nxt][lk + 3][lr] = av.w;
            Ws[nxt][lk + 0][lr] = wv.x; Ws[nxt][lk + 1][lr] = wv.y;
            Ws[nxt][lk + 2][lr] = wv.z; Ws[nxt][lk + 3][lr] = wv.w;
            __syncthreads();
        }
    }

#pragma unroll
    for (int ih = 0; ih < 2; ih++)
#pragma unroll
    for (int i = 0; i < 4; i++) {
        int gm = bm0 + tm * 4 + ih * 64 + i;
#pragma unroll
        for (int jh = 0; jh < 2; jh++)
#pragma unroll
        for (int j = 0; j < 4; j++) {
            int gn = bn0 + tn * 4 + jh * 64 + j;
            if (gn >= N) continue;
            float v = acc[ih * 4 + i][jh * 4 + j];
            if (bias) v += bias[gn];
            if (act == 1) v = softplus_f(v);
            else if (act == 2) v = gelu_f(v);
            if (res) v += res[(size_t)gm * ldc + gn];
            C[(size_t)gm * ldc + gn] = v;
        }
    }
}

// ---------------- causal conv1d (width 4) + silu, vectorized ----------------
__global__ void conv_silu_k(const float* __restrict__ xz, const float* __restrict__ cw,
                            const float* __restrict__ cb, float* __restrict__ xc)
{
    int idx = blockIdx.x * blockDim.x + threadIdx.x;
    if (idx >= NROW * DI / 4) return;
    int e4 = (idx % (DI / 4)) * 4;
    int bl = idx / (DI / 4);
    int b = bl / LSEQ, l = bl % LSEQ;

    float4 w0 = *(const float4*)(cw + (e4 + 0) * 4);
    float4 w1 = *(const float4*)(cw + (e4 + 1) * 4);
    float4 w2 = *(const float4*)(cw + (e4 + 2) * 4);
    float4 w3 = *(const float4*)(cw + (e4 + 3) * 4);

    float4 xv[4];
#pragma unroll
    for (int k = 0; k < 4; k++) {
        int ll = l + k - 3;
        xv[k] = (ll >= 0)
            ? *(const float4*)(xz + ((size_t)b * LSEQ + ll) * (2 * DI) + e4)
            : make_float4(0.f, 0.f, 0.f, 0.f);
    }

    float4 acc = *(const float4*)(cb + e4);
    acc.x += w0.x * xv[0].x + w0.y * xv[1].x + w0.z * xv[2].x + w0.w * xv[3].x;
    acc.y += w1.x * xv[0].y + w1.y * xv[1].y + w1.z * xv[2].y + w1.w * xv[3].y;
    acc.z += w2.x * xv[0].z + w2.y * xv[1].z + w2.z * xv[2].z + w2.w * xv[3].z;
    acc.w += w3.x * xv[0].w + w3.y * xv[1].w + w3.z * xv[2].w + w3.w * xv[3].w;

    acc.x = acc.x / (1.f + __expf(-acc.x));
    acc.y = acc.y / (1.f + __expf(-acc.y));
    acc.z = acc.z / (1.f + __expf(-acc.z));
    acc.w = acc.w / (1.f + __expf(-acc.w));
    *(float4*)(xc + (size_t)bl * DI + e4) = acc;
}

// ================= chunked selective scan =================
__device__ __forceinline__ bool load_A(const float* __restrict__ A_log, int d, float* A) {
    bool structured = true;
#pragma unroll
    for (int n = 0; n < DS; n++) A[n] = -__expf(A_log[d * DS + n]);
#pragma unroll
    for (int n = 1; n < DS; n++) {
        float want = (n + 1) * A[0];
        structured &= fabsf(A[n] - want) <= 1e-4f * fabsf(want);
    }
    return structured;
}

__global__ __launch_bounds__(256) void scan_chunk_partial(
    const float* __restrict__ dt, const float* __restrict__ xc,
    const float* __restrict__ dbl, const float* __restrict__ A_log,
    float* __restrict__ Pout, float* __restrict__ Sout)
{
    __shared__ float sB[CS][DS];
    int d = blockIdx.x * 256 + threadIdx.x;
    int c = blockIdx.y;
    int b = blockIdx.z;
    int l0 = c * CS;

    for (int i = threadIdx.x; i < CS * DS; i += 256) {
        int s = i / DS, j = i % DS;
        sB[s][j] = dbl[((size_t)(b * LSEQ + l0 + s)) * XCOLS + DTR + j];
    }
    __syncthreads();

    float A[DS];
    bool structured = load_A(A_log, d, A);
    float A0 = A[0];

    float P[DS], S[DS];
#pragma unroll
    for (int n = 0; n < DS; n++) { P[n] = 1.f; S[n] = 0.f; }

    const float* dtp = dt + (size_t)(b * LSEQ + l0) * DI + d;
    const float* xcp = xc + (size_t)(b * LSEQ + l0) * DI + d;

    if (structured) {
        for (int s = 0; s < CS; s++) {
            float dtv = dtp[(size_t)s * DI];
            float xv  = xcp[(size_t)s * DI];
            float w = dtv * xv;
            float e1 = __expf(dtv * A0);
            float ee = 1.f;
#pragma unroll
            for (int n = 0; n < DS; n++) {
                ee *= e1;
                P[n] *= ee;
                S[n] = ee * S[n] + w * sB[s][n];
            }
        }
    } else {
        for (int s = 0; s < CS; s++) {
            float dtv = dtp[(size_t)s * DI];
            float xv  = xcp[(size_t)s * DI];
            float w = dtv * xv;
#pragma unroll
            for (int n = 0; n < DS; n++) {
                float ee = __expf(dtv * A[n]);
                P[n] *= ee;
                S[n] = ee * S[n] + w * sB[s][n];
            }
        }
    }

    size_t base = ((size_t)(b * NC + c) * DI + d) * DS;
#pragma unroll
    for (int n = 0; n < DS; n++) { Pout[base + n] = P[n]; Sout[base + n] = S[n]; }
}

__global__ __launch_bounds__(256) void scan_chunk_seq(
    const float* __restrict__ P, const float* __restrict__ S, float* __restrict__ h0)
{
    int idx = blockIdx.x * blockDim.x + threadIdx.x;
    if (idx >= BSZ * DI * DS) return;
    int b = idx / (DI * DS);
    int r = idx % (DI * DS);
    float h = 0.f;
    for (int c = 0; c < NC; c++) {
        size_t off = (size_t)b * NC * DI * DS + (size_t)c * DI * DS + r;
        h0[off] = h;
        h = P[off] * h + S[off];
    }
}

__global__ __launch_bounds__(256) void scan_chunk_final(
    const float* __restrict__ dt, const float* __restrict__ xc,
    const float* __restrict__ dbl, const float* __restrict__ xz,
    const float* __restrict__ A_log, const float* __restrict__ Dp,
    const float* __restrict__ h0, float* __restrict__ y)
{
    __shared__ float sBC[CS][2 * DS];
    int d = blockIdx.x * 256 + threadIdx.x;
    int c = blockIdx.y;
    int b = blockIdx.z;
    int l0 = c * CS;

    for (int i = threadIdx.x; i < CS * 2 * DS; i += 256) {
        int s = i / (2 * DS), j = i % (2 * DS);
        sBC[s][j] = dbl[((size_t)(b * LSEQ + l0 + s)) * XCOLS + DTR + j];
    }
    __syncthreads();

    float A[DS];
    bool structured = load_A(A_log, d, A);
    float A0 = A[0];
    float Dv = Dp[d];

    float h[DS];
    size_t hbase = ((size_t)(b * NC + c) * DI + d) * DS;
#pragma unroll
    for (int n = 0; n < DS; n++) h[n] = h0[hbase + n];

    const float* dtp = dt + (size_t)(b * LSEQ + l0) * DI + d;
    const float* xcp = xc + (size_t)(b * LSEQ + l0) * DI + d;
    const float* zp  = xz + (size_t)(b * LSEQ + l0) * 2 * DI + DI + d;
    float* yp = y + (size_t)(b * LSEQ + l0) * DI + d;

    if (structured) {
        for (int s = 0; s < CS; s++) {
            float dtv = dtp[(size_t)s * DI];
            float xv  = xcp[(size_t)s * DI];
            float w = dtv * xv;
            float e1 = __expf(dtv * A0);
            float ee = 1.f;
            float ya = 0.f;
#pragma unroll
            for (int n = 0; n < DS; n++) {
                ee *= e1;
                h[n] = ee * h[n] + w * sBC[s][n];
                ya += h[n] * sBC[s][DS + n];
            }
            float zv = zp[(size_t)s * 2 * DI];
            float sil = zv / (1.f + __expf(-zv));
            yp[(size_t)s * DI] = (ya + Dv * xv) * sil;
        }
    } else {
        for (int s = 0; s < CS; s++) {
            float dtv = dtp[(size_t)s * DI];
            float xv  = xcp[(size_t)s * DI];
            float w = dtv * xv;
            float ya = 0.f;
#pragma unroll
            for (int n = 0; n < DS; n++) {
                float ee = __expf(dtv * A[n]);
                h[n] = ee * h[n] + w * sBC[s][n];
                ya += h[n] * sBC[s][DS + n];
            }
            float zv = zp[(size_t)s * 2 * DI];
            float sil = zv / (1.f + __expf(-zv));
            yp[(size_t)s * DI] = (ya + Dv * xv) * sil;
        }
    }
}

// ---------------- fused max-pool + classifier head ----------------
__global__ void poolhead_k(const float* __restrict__ h, const float* __restrict__ hw,
                           const float* __restrict__ hb, float* __restrict__ out)
{
    int n = blockIdx.x;        // 0..31
    int t = threadIdx.x;       // 0..383
    const float* base = h + (size_t)n * 196 * DM + t;
    float m = -1e30f;
    for (int p = 0; p < 196; p++) m = fmaxf(m, base[(size_t)p * DM]);
    __shared__ float sp[DM];
    sp[t] = m;
    __syncthreads();
    if (t < 96) {
        int c = t / 32, lane = t % 32;
        float acc = 0.f;
        for (int k = lane; k < DM; k += 32) acc += sp[k] * hw[c * DM + k];
#pragma unroll
        for (int o = 16; o; o >>= 1) acc += __shfl_xor_sync(0xffffffffu, acc, o);
        if (lane == 0) out[n * 3 + c] = acc + hb[c];
    }
}

// ---------------- host orchestration ----------------
static void mma_call(const float* A, int lda, const bf16* Wh, const bf16* Wl,
                     int N, int K, float* C, int ldc,
                     const float* bias, const float* res, int act, int nReal,
                     const float2* lnStat = nullptr,
                     const float* lnG = nullptr, const float* lnB = nullptr)
{
    dim3 grid(N / 64, NROW / 128);
    mma_gemm<<<grid, 256, MG_SMEM>>>(A, lda, Wh, Wl, K, C, ldc,
                                     bias, res, K, act, nReal, lnStat, lnG, lnB);
}

extern "C" void kernel_launch(void* const* d_in, const int* in_sizes, int n_in,
                              void* d_out, int out_size)
{
    const float* x       = (const float*)d_in[0];
    const float* patch_w = (const float*)d_in[1];
    const float* patch_b = (const float*)d_in[2];
    const float* ln1_g   = (const float*)d_in[3];
    const float* ln1_b   = (const float*)d_in[4];
    const float* in_w    = (const float*)d_in[5];
    const float* conv_w  = (const float*)d_in[6];
    const float* conv_b  = (const float*)d_in[7];
    const float* xproj_w = (const float*)d_in[8];
    const float* dt_w    = (const float*)d_in[9];
    const float* dt_b    = (const float*)d_in[10];
    const float* A_log   = (const float*)d_in[11];
    const float* Dparam  = (const float*)d_in[12];
    const float* out_w   = (const float*)d_in[13];
    const float* ln2_g   = (const float*)d_in[14];
    const float* ln2_b   = (const float*)d_in[15];
    const float* fc1_w   = (const float*)d_in[16];
    const float* fc1_b   = (const float*)d_in[17];
    const float* fc2_w   = (const float*)d_in[18];
    const float* fc2_b   = (const float*)d_in[19];
    const float* head_w  = (const float*)d_in[20];
    const float* head_b  = (const float*)d_in[21];
    float* out = (float*)d_out;

    cudaFuncSetAttribute(mma_gemm, cudaFuncAttributeMaxDynamicSharedMemorySize, MG_SMEM);

    float *xf, *h, *xz, *xc, *dbl, *dt, *y, *m1, *P, *S, *h0;
    float2* stat;
    bf16 *wh, *wl;
    cudaGetSymbolAddress((void**)&xf,  g_xf);
    cudaGetSymbolAddress((void**)&h,   g_h);
    cudaGetSymbolAddress((void**)&stat, g_stat);
    cudaGetSymbolAddress((void**)&xz,  g_xz);
    cudaGetSymbolAddress((void**)&xc,  g_xc);
    cudaGetSymbolAddress((void**)&dbl, g_dbl);
    cudaGetSymbolAddress((void**)&dt,  g_dt);
    cudaGetSymbolAddress((void**)&y,   g_y);
    cudaGetSymbolAddress((void**)&m1,  g_m1);
    cudaGetSymbolAddress((void**)&P,   g_P);
    cudaGetSymbolAddress((void**)&S,   g_S);
    cudaGetSymbolAddress((void**)&h0,  g_h0);
    cudaGetSymbolAddress((void**)&wh,  g_wh);
    cudaGetSymbolAddress((void**)&wl,  g_wl);

    // --- convert all weights upfront (6 launches; overlaps patchify) ---
    wcvt_k<<<296, 256>>>(patch_w, wh + WOFF_PATCH, wl + WOFF_PATCH, WSZ_PATCH);
    wcvt_k<<<592, 256>>>(in_w,  wh + WOFF_INW,  wl + WOFF_INW,  4 * WSZ_INW);
    wcvt_k<<<592, 256>>>(out_w, wh + WOFF_OUTW, wl + WOFF_OUTW, 4 * WSZ_OUTW);
    wcvt_k<<<592, 256>>>(fc1_w, wh + WOFF_FC1,  wl + WOFF_FC1,  4 * WSZ_FC1);
    wcvt_k<<<592, 256>>>(fc2_w, wh + WOFF_FC2,  wl + WOFF_FC2,  4 * WSZ_FC2);
    wcvt_xpj_k<<<(4 * WSZ_XPJ + 255) / 256, 256>>>(xproj_w, wh + WOFF_XPJ, wl + WOFF_XPJ);

    // patchify + patch embed -> h
    gather_patches_k<<<(NROW * DI + 255) / 256, 256>>>(x, xf);
    mma_call(xf, DI, wh + WOFF_PATCH, wl + WOFF_PATCH, DM, DI,
             h, DM, patch_b, nullptr, 0, DM);

    for (int i = 0; i < 4; i++) {
        const bf16* inwh = wh + WOFF_INW + (size_t)i * WSZ_INW;
        const bf16* inwl = wl + WOFF_INW + (size_t)i * WSZ_INW;
        const bf16* owh  = wh + WOFF_OUTW + (size_t)i * WSZ_OUTW;
        const bf16* owl  = wl + WOFF_OUTW + (size_t)i * WSZ_OUTW;
        const bf16* f1h  = wh + WOFF_FC1 + (size_t)i * WSZ_FC1;
        const bf16* f1l  = wl + WOFF_FC1 + (size_t)i * WSZ_FC1;
        const bf16* f2h  = wh + WOFF_FC2 + (size_t)i * WSZ_FC2;
        const bf16* f2l  = wl + WOFF_FC2 + (size_t)i * WSZ_FC2;
        const bf16* xph  = wh + WOFF_XPJ + (size_t)i * WSZ_XPJ;
        const bf16* xpl  = wl + WOFF_XPJ + (size_t)i * WSZ_XPJ;

        // --- mamba block (LN1 fused into in_proj A-load) ---
        rowstat_k<<<NROW, 128>>>(h, stat);
        mma_call(h, DM, inwh, inwl, 2 * DI, DM,
                 xz, 2 * DI, nullptr, nullptr, 0, 2 * DI,
                 stat, ln1_g + i * DM, ln1_b + i * DM);
        conv_silu_k<<<(NROW * DI / 4 + 255) / 256, 256>>>(
            xz, conv_w + (size_t)i * DI * 4, conv_b + (size_t)i * DI, xc);
        // xproj on tensor cores (padded N=64, real 52)
        mma_call(xc, DI, xph, xpl, XPAD, DI,
                 dbl, XCOLS, nullptr, nullptr, 0, XCOLS);
        {
            dim3 grid((DI + TBN - 1) / TBN, NROW / TBM);
            sgemm128<<<grid, 256>>>(dbl, XCOLS, dt_w + (size_t)i * DI * DTR, DTR,
                                    dt, DI, dt_b + (size_t)i * DI, nullptr,
                                    DI, DTR, 1 /*softplus*/);
        }

        // --- chunked selective scan ---
        {
            dim3 gA(DI / 256, NC, BSZ);
            scan_chunk_partial<<<gA, 256>>>(dt, xc, dbl,
                                            A_log + (size_t)i * DI * DS, P, S);
            scan_chunk_seq<<<(BSZ * DI * DS + 255) / 256, 256>>>(P, S, h0);
            scan_chunk_final<<<gA, 256>>>(dt, xc, dbl, xz,
                                          A_log + (size_t)i * DI * DS,
                                          Dparam + (size_t)i * DI, h0, y);
        }

        mma_call(y, DI, owh, owl, DM, DI,
                 h, DM, nullptr, h /*residual*/, 0, DM);

        // --- mlp block (LN2 fused into fc1 A-load) ---
        rowstat_k<<<NROW, 128>>>(h, stat);
        mma_call(h, DM, f1h, f1l, DHID, DM,
                 m1, DHID, fc1_b + (size_t)i * DHID, nullptr, 2 /*gelu*/, DHID,
                 stat, ln2_g + i * DM, ln2_b + i * DM);
        mma_call(m1, DHID, f2h, f2l, DM, DHID,
                 h, DM, fc2_b + (size_t)i * DM, h /*residual*/, 0, DM);
    }

    poolhead_k<<<32, DM>>>(h, head_w, head_b, out);
}

// round 15
// speedup vs baseline: 1.0423x; 1.0423x over previous
#include <cuda_runtime.h>
#include <cuda_bf16.h>
#include <cstdint>
#include <cstdio>

// ---------------- problem constants ----------------
#define BSZ    2
#define TT     16
#define LSEQ   3136          // TT * 196
#define NROW   6272          // BSZ * LSEQ (== 49*128)
#define DM     384
#define DI     768
#define DS     14
#define DTR    24
#define XCOLS  52            // DTR + 2*DS
#define XPAD   64            // xproj weight padded rows
#define DHID   1536          // 4*DM == 2*DI

// chunked scan
#define NC     56
#define CS     56

typedef __nv_bfloat16 bf16;

// weight arena offsets (elements)
#define WOFF_PATCH 0
#define WSZ_PATCH  (DM * DI)
#define WOFF_INW   (WOFF_PATCH + WSZ_PATCH)
#define WSZ_INW    (2 * DI * DM)
#define WOFF_OUTW  (WOFF_INW + 4 * WSZ_INW)
#define WSZ_OUTW   (DM * DI)
#define WOFF_FC1   (WOFF_OUTW + 4 * WSZ_OUTW)
#define WSZ_FC1    (DHID * DM)
#define WOFF_FC2   (WOFF_FC1 + 4 * WSZ_FC1)
#define WSZ_FC2    (DM * DHID)
#define WOFF_XPJ   (WOFF_FC2 + 4 * WSZ_FC2)
#define WSZ_XPJ    (XPAD * DI)                 // padded 64x768 per layer
#define WARENA     (WOFF_XPJ + 4 * WSZ_XPJ)

// ---------------- scratch ----------------
__device__ float g_xf [NROW * DI];
__device__ float g_h  [NROW * DM];
__device__ float g_ln [NROW * DM];
__device__ float g_xz [NROW * 2 * DI];
__device__ float g_xc [NROW * DI];
__device__ float g_dbl[NROW * XCOLS];
__device__ float g_dt [NROW * DI];
__device__ float g_y  [NROW * DI];
__device__ float g_m1 [NROW * DHID];
__device__ float g_P  [BSZ * NC * DI * DS];
__device__ float g_S  [BSZ * NC * DI * DS];
__device__ float g_h0 [BSZ * NC * DI * DS];
// persistent hi/lo weight arena (all layers)
__device__ __align__(16) bf16 g_wh[WARENA];
__device__ __align__(16) bf16 g_wl[WARENA];

// ---------------- activations ----------------
__device__ __forceinline__ float softplus_f(float x) {
    return fmaxf(x, 0.f) + log1pf(expf(-fabsf(x)));
}
__device__ __forceinline__ float gelu_f(float x) {
    float x3 = x * x * x;
    float t = tanhf(0.7978845608028654f * (x + 0.044715f * x3));
    return 0.5f * x * (1.f + t);
}

__device__ __forceinline__ uint32_t smem_u32(const void* p) {
    uint32_t a;
    asm("{ .reg .u64 t; cvta.to.shared.u64 t, %1; cvt.u32.u64 %0, t; }" : "=r"(a) : "l"(p));
    return a;
}

__device__ __forceinline__ void split_bf16(float v, bf16& hi, bf16& lo) {
    hi = __float2bfloat16(v);
    lo = __float2bfloat16(v - __bfloat162float(hi));
}

// ================= bf16-split tensor-core GEMM (mma.sync) =================
// C[M,N] = act(A[M,K]*W^T + bias) + res.  A fp32 (split in-kernel);
// W pre-split bf16 hi/lo from the arena.  M%128==0, N%64==0, K%32==0.
// Warp tile 32x32 (8 warps as 4x2).
#define KB 32
#define SROW 40
#define MG_AH 0
#define MG_AL 10240
#define MG_WH 20480
#define MG_WL 25600
#define MG_STAGE 30720
#define MG_SMEM (2 * MG_STAGE)

__device__ __forceinline__ void ldm_x4(uint32_t& r0, uint32_t& r1, uint32_t& r2,
                                       uint32_t& r3, uint32_t addr) {
    asm volatile("ldmatrix.sync.aligned.m8n8.x4.shared.b16 {%0,%1,%2,%3}, [%4];"
                 : "=r"(r0), "=r"(r1), "=r"(r2), "=r"(r3) : "r"(addr));
}
__device__ __forceinline__ void mma_bf16(float* d, const uint32_t* a,
                                         uint32_t b0, uint32_t b1) {
    asm volatile(
        "mma.sync.aligned.m16n8k16.row.col.f32.bf16.bf16.f32 "
        "{%0,%1,%2,%3}, {%4,%5,%6,%7}, {%8,%9}, {%0,%1,%2,%3};"
        : "+f"(d[0]), "+f"(d[1]), "+f"(d[2]), "+f"(d[3])
        : "r"(a[0]), "r"(a[1]), "r"(a[2]), "r"(a[3]), "r"(b0), "r"(b1));
}

__device__ __forceinline__ void cvt_split4(float4 v, uint16_t* hi, uint16_t* lo) {
    __nv_bfloat16 hx = __float2bfloat16(v.x), hy = __float2bfloat16(v.y);
    __nv_bfloat16 hz = __float2bfloat16(v.z), hw = __float2bfloat16(v.w);
    __nv_bfloat16 gx = __float2bfloat16(v.x - __bfloat162float(hx));
    __nv_bfloat16 gy = __float2bfloat16(v.y - __bfloat162float(hy));
    __nv_bfloat16 gz = __float2bfloat16(v.z - __bfloat162float(hz));
    __nv_bfloat16 gw = __float2bfloat16(v.w - __bfloat162float(hw));
    uint2 hp, lp;
    hp.x = (uint32_t)__bfloat16_as_ushort(hy) << 16 | __bfloat16_as_ushort(hx);
    hp.y = (uint32_t)__bfloat16_as_ushort(hw) << 16 | __bfloat16_as_ushort(hz);
    lp.x = (uint32_t)__bfloat16_as_ushort(gy) << 16 | __bfloat16_as_ushort(gx);
    lp.y = (uint32_t)__bfloat16_as_ushort(gw) << 16 | __bfloat16_as_ushort(gz);
    *(uint2*)hi = hp;
    *(uint2*)lo = lp;
}

__global__ __launch_bounds__(256, 2) void mma_gemm(
    const float* __restrict__ A, int lda,
    const bf16* __restrict__ Wh, const bf16* __restrict__ Wl, int ldw,
    float* __restrict__ C, int ldc,
    const float* __restrict__ bias,
    const float* __restrict__ res,
    int K, int act, int nReal)
{
    extern __shared__ __align__(16) char dsm[];

    int tid  = threadIdx.x;
    int wid  = tid >> 5;
    int lane = tid & 31;
    int bm0 = blockIdx.y * 128;
    int bn0 = blockIdx.x * 64;
    int wm = (wid >> 1) * 32;   // 0/32/64/96
    int wn = (wid & 1) * 32;    // 0/32

    float acc[2][4][4];
#pragma unroll
    for (int mt = 0; mt < 2; mt++)
#pragma unroll
        for (int nt = 0; nt < 4; nt++)
#pragma unroll
            for (int i = 0; i < 4; i++) acc[mt][nt][i] = 0.f;

    int lrA[4], lcA[4];
#pragma unroll
    for (int i = 0; i < 4; i++) {
        int idx = i * 256 + tid;
        lrA[i] = idx >> 3;
        lcA[i] = (idx & 7) * 4;
    }
    int wr = tid >> 2, wc = (tid & 3) * 8;
    uint32_t oW = (uint32_t)(wr * SROW + wc) * 2;

    const bf16* gWh = Wh + (size_t)(bn0 + wr) * ldw + wc;
    const bf16* gWl = Wl + (size_t)(bn0 + wr) * ldw + wc;

    float4 pa[4];
    uint4 pwh, pwl;
#pragma unroll
    for (int i = 0; i < 4; i++)
        pa[i] = *(const float4*)(A + (size_t)(bm0 + lrA[i]) * lda + lcA[i]);
    pwh = *(const uint4*)gWh;
    pwl = *(const uint4*)gWl;

    {
        char* sn = dsm;
#pragma unroll
        for (int i = 0; i < 4; i++) {
            int o = lrA[i] * SROW + lcA[i];
            cvt_split4(pa[i], (uint16_t*)(sn + MG_AH) + o, (uint16_t*)(sn + MG_AL) + o);
        }
        *(uint4*)(sn + MG_WH + oW) = pwh;
        *(uint4*)(sn + MG_WL + oW) = pwl;
    }
    __syncthreads();

    uint32_t sAh[2], sAl[2], sWh[2], sWl[2];
#pragma unroll
    for (int s = 0; s < 2; s++) {
        sAh[s] = smem_u32(dsm + s * MG_STAGE + MG_AH);
        sAl[s] = smem_u32(dsm + s * MG_STAGE + MG_AL);
        sWh[s] = smem_u32(dsm + s * MG_STAGE + MG_WH);
        sWl[s] = smem_u32(dsm + s * MG_STAGE + MG_WL);
    }

    int frow = lane & 15;
    int fk   = (lane >> 4) << 3;

    int nch = K / KB;
    for (int c = 0; c < nch; c++) {
        int cur = c & 1, nxt = cur ^ 1;

        if (c + 1 < nch) {
            int ko = (c + 1) * KB;
#pragma unroll
            for (int i = 0; i < 4; i++)
                pa[i] = *(const float4*)(A + (size_t)(bm0 + lrA[i]) * lda + ko + lcA[i]);
            pwh = *(const uint4*)(gWh + ko);
            pwl = *(const uint4*)(gWl + ko);
        }

#pragma unroll
        for (int k0 = 0; k0 < KB; k0 += 16) {
            // W fragments: 32 cols of this warp, hi and lo (4 ldmatrix)
            uint32_t bh[4][2], bl[4][2];
#pragma unroll
            for (int nh = 0; nh < 2; nh++) {
                uint32_t off = (uint32_t)((wn + nh * 16 + frow) * SROW + k0 + fk) * 2;
                uint32_t r0, r1, r2, r3;
                ldm_x4(r0, r1, r2, r3, sWh[cur] + off);
                bh[nh * 2 + 0][0] = r0; bh[nh * 2 + 0][1] = r2;
                bh[nh * 2 + 1][0] = r1; bh[nh * 2 + 1][1] = r3;
                ldm_x4(r0, r1, r2, r3, sWl[cur] + off);
                bl[nh * 2 + 0][0] = r0; bl[nh * 2 + 0][1] = r2;
                bl[nh * 2 + 1][0] = r1; bl[nh * 2 + 1][1] = r3;
            }
            // A fragments: 32 rows, hi and lo (4 ldmatrix), then 24 MMA
#pragma unroll
            for (int mt = 0; mt < 2; mt++) {
                uint32_t off = (uint32_t)((wm + mt * 16 + frow) * SROW + k0 + fk) * 2;
                uint32_t ah[4], al[4];
                ldm_x4(ah[0], ah[1], ah[2], ah[3], sAh[cur] + off);
                ldm_x4(al[0], al[1], al[2], al[3], sAl[cur] + off);
#pragma unroll
                for (int nt = 0; nt < 4; nt++) {
                    mma_bf16(acc[mt][nt], ah, bh[nt][0], bh[nt][1]);
                    mma_bf16(acc[mt][nt], ah, bl[nt][0], bl[nt][1]);
                    mma_bf16(acc[mt][nt], al, bh[nt][0], bh[nt][1]);
                }
            }
        }

        if (c + 1 < nch) {
            char* sn = dsm + nxt * MG_STAGE;
#pragma unroll
            for (int i = 0; i < 4; i++) {
                int o = lrA[i] * SROW + lcA[i];
                cvt_split4(pa[i], (uint16_t*)(sn + MG_AH) + o, (uint16_t*)(sn + MG_AL) + o);
            }
            *(uint4*)(sn + MG_WH + oW) = pwh;
            *(uint4*)(sn + MG_WL + oW) = pwl;
            __syncthreads();
        }
    }

    // epilogue: fragment row = lane/4 (+8), col = (lane%4)*2 (+1)
    int gq = lane >> 2;
    int gr = (lane & 3) * 2;
#pragma unroll
    for (int mt = 0; mt < 2; mt++) {
#pragma unroll
        for (int half = 0; half < 2; half++) {
            int gm = bm0 + wm + mt * 16 + gq + half * 8;
            float* crow = C + (size_t)gm * ldc;
            const float* rrow = res ? res + (size_t)gm * ldc : nullptr;
#pragma unroll
            for (int nt = 0; nt < 4; nt++) {
                int gn = bn0 + wn + nt * 8 + gr;
                if (gn >= nReal) continue;
                float v0 = acc[mt][nt][half * 2 + 0];
                float v1 = acc[mt][nt][half * 2 + 1];
                if (bias) { v0 += bias[gn]; v1 += bias[gn + 1]; }
                if (act == 2)      { v0 = gelu_f(v0);     v1 = gelu_f(v1); }
                else if (act == 1) { v0 = softplus_f(v0); v1 = softplus_f(v1); }
                if (rrow) { v0 += rrow[gn]; v1 += rrow[gn + 1]; }
                *(float2*)(crow + gn) = make_float2(v0, v1);
            }
        }
    }
}

// ---------------- weight fp32 -> bf16 hi/lo (grid-strided) ----------------
__global__ void wcvt_k(const float* __restrict__ w, bf16* __restrict__ hi,
                       bf16* __restrict__ lo, int n) {
    for (int i = blockIdx.x * 256 + threadIdx.x; i < n; i += gridDim.x * 256) {
        bf16 h, l;
        split_bf16(w[i], h, l);
        hi[i] = h; lo[i] = l;
    }
}

// xproj weights: pad 52 rows -> 64 rows (zeros), all 4 layers in one launch
__global__ void wcvt_xpj_k(const float* __restrict__ w, bf16* __restrict__ hi,
                           bf16* __restrict__ lo) {
    int i = blockIdx.x * 256 + threadIdx.x;
    if (i >= 4 * XPAD * DI) return;
    int layer = i / (XPAD * DI);
    int rem = i % (XPAD * DI);
    int row = rem / DI;
    int col = rem % DI;
    float v = (row < XCOLS) ? w[((size_t)layer * XCOLS + row) * DI + col] : 0.f;
    bf16 h, l;
    split_bf16(v, h, l);
    hi[i] = h; lo[i] = l;
}

// ---------------- patchify gather ----------------
__global__ void gather_patches_k(const float* __restrict__ x, float* __restrict__ xf) {
    int idx = blockIdx.x * blockDim.x + threadIdx.x;
    if (idx >= NROW * DI) return;
    int c   = idx % DI;
    int row = idx / DI;
    int n  = row / 196, p = row % 196;
    int ph = p / 14,   pw = p % 14;
    int ch = c >> 8;
    int rem = c & 255;
    int py = rem >> 4, px = rem & 15;
    xf[idx] = x[((size_t)(n * 3 + ch) * 224 + (ph * 16 + py)) * 224 + (pw * 16 + px)];
}

// ================= FFMA 128x128 double-buffered SGEMM (K%8==0, for dt) ===========
#define TBM 128
#define TBN 128
#define TBK 8
__global__ __launch_bounds__(256, 2) void sgemm128(
    const float* __restrict__ A, int lda,
    const float* __restrict__ W, int ldw,
    float* __restrict__ C, int ldc,
    const float* __restrict__ bias,
    const float* __restrict__ res,
    int N, int K, int act)
{
    __shared__ __align__(16) float As[2][TBK][TBM];
    __shared__ __align__(16) float Ws[2][TBK][TBN];

    int bm0 = blockIdx.y * TBM;
    int bn0 = blockIdx.x * TBN;
    int tid = threadIdx.x;
    int tm = tid >> 4;
    int tn = tid & 15;
    int lr = tid >> 1;
    int lk = (tid & 1) * 4;

    const float* Aptr = A + (size_t)(bm0 + lr) * lda + lk;
    bool wok = (bn0 + lr) < N;
    const float* Wptr = W + (size_t)(wok ? (bn0 + lr) : 0) * ldw + lk;

    float4 av = *(const float4*)Aptr;
    float4 wv = wok ? *(const float4*)Wptr : make_float4(0.f, 0.f, 0.f, 0.f);
    As[0][lk + 0][lr] = av.x; As[0][lk + 1][lr] = av.y;
    As[0][lk + 2][lr] = av.z; As[0][lk + 3][lr] = av.w;
    Ws[0][lk + 0][lr] = wv.x; Ws[0][lk + 1][lr] = wv.y;
    Ws[0][lk + 2][lr] = wv.z; Ws[0][lk + 3][lr] = wv.w;
    __syncthreads();

    float acc[8][8];
#pragma unroll
    for (int i = 0; i < 8; i++)
#pragma unroll
        for (int j = 0; j < 8; j++) acc[i][j] = 0.f;

    int nk = K / TBK;
    for (int kt = 0; kt < nk; kt++) {
        int cur = kt & 1, nxt = cur ^ 1;
        if (kt + 1 < nk) {
            av = *(const float4*)(Aptr + (size_t)(kt + 1) * TBK);
            wv = wok ? *(const float4*)(Wptr + (size_t)(kt + 1) * TBK)
                     : make_float4(0.f, 0.f, 0.f, 0.f);
        }
#pragma unroll
        for (int kk = 0; kk < TBK; kk++) {
            float4 a0 = *(const float4*)&As[cur][kk][tm * 4];
            float4 a1 = *(const float4*)&As[cur][kk][tm * 4 + 64];
            float4 w0 = *(const float4*)&Ws[cur][kk][tn * 4];
            float4 w1 = *(const float4*)&Ws[cur][kk][tn * 4 + 64];
            float a[8] = {a0.x, a0.y, a0.z, a0.w, a1.x, a1.y, a1.z, a1.w};
            float w[8] = {w0.x, w0.y, w0.z, w0.w, w1.x, w1.y, w1.z, w1.w};
#pragma unroll
            for (int i = 0; i < 8; i++)
#pragma unroll
                for (int j = 0; j < 8; j++)
                    acc[i][j] = fmaf(a[i], w[j], acc[i][j]);
        }
        if (kt + 1 < nk) {
            As[nxt][lk + 0][lr] = av.x; As[nxt][lk + 1][lr] = av.y;
            As[nxt][lk + 2][lr] = av.z; As[nxt][lk + 3][lr] = av.w;
            Ws[nxt][lk + 0][lr] = wv.x; Ws[nxt][lk + 1][lr] = wv.y;
            Ws[nxt][lk + 2][lr] = wv.z; Ws[nxt][lk + 3][lr] = wv.w;
            __syncthreads();
        }
    }

#pragma unroll
    for (int ih = 0; ih < 2; ih++)
#pragma unroll
    for (int i = 0; i < 4; i++) {
        int gm = bm0 + tm * 4 + ih * 64 + i;
#pragma unroll
        for (int jh = 0; jh < 2; jh++)
#pragma unroll
        for (int j = 0; j < 4; j++) {
            int gn = bn0 + tn * 4 + jh * 64 + j;
            if (gn >= N) continue;
            float v = acc[ih * 4 + i][jh * 4 + j];
            if (bias) v += bias[gn];
            if (act == 1) v = softplus_f(v);
            else if (act == 2) v = gelu_f(v);
            if (res) v += res[(size_t)gm * ldc + gn];
            C[(size_t)gm * ldc + gn] = v;
        }
    }
}

// ---------------- layernorm ----------------
__global__ void layernorm_k(const float* __restrict__ x, const float* __restrict__ g,
                            const float* __restrict__ b, float* __restrict__ out)
{
    int row = blockIdx.x;
    int t = threadIdx.x;
    const float* xr = x + (size_t)row * DM;
    float v0 = xr[t], v1 = xr[t + 128], v2 = xr[t + 256];
    float s  = v0 + v1 + v2;
    float s2 = v0 * v0 + v1 * v1 + v2 * v2;
#pragma unroll
    for (int o = 16; o; o >>= 1) {
        s  += __shfl_xor_sync(0xffffffffu, s,  o);
        s2 += __shfl_xor_sync(0xffffffffu, s2, o);
    }
    __shared__ float ss[4], ss2[4];
    int w = t >> 5;
    if ((t & 31) == 0) { ss[w] = s; ss2[w] = s2; }
    __syncthreads();
    s  = ss[0] + ss[1] + ss[2] + ss[3];
    s2 = ss2[0] + ss2[1] + ss2[2] + ss2[3];
    float mu  = s * (1.f / DM);
    float var = s2 * (1.f / DM) - mu * mu;
    float r = rsqrtf(var + 1e-5f);
    float* orow = out + (size_t)row * DM;
    orow[t]       = (v0 - mu) * r * g[t]       + b[t];
    orow[t + 128] = (v1 - mu) * r * g[t + 128] + b[t + 128];
    orow[t + 256] = (v2 - mu) * r * g[t + 256] + b[t + 256];
}

// ---------------- causal conv1d (width 4) + silu, vectorized ----------------
__global__ void conv_silu_k(const float* __restrict__ xz, const float* __restrict__ cw,
                            const float* __restrict__ cb, float* __restrict__ xc)
{
    int idx = blockIdx.x * blockDim.x + threadIdx.x;
    if (idx >= NROW * DI / 4) return;
    int e4 = (idx % (DI / 4)) * 4;
    int bl = idx / (DI / 4);
    int b = bl / LSEQ, l = bl % LSEQ;

    float4 w0 = *(const float4*)(cw + (e4 + 0) * 4);
    float4 w1 = *(const float4*)(cw + (e4 + 1) * 4);
    float4 w2 = *(const float4*)(cw + (e4 + 2) * 4);
    float4 w3 = *(const float4*)(cw + (e4 + 3) * 4);

    float4 xv[4];
#pragma unroll
    for (int k = 0; k < 4; k++) {
        int ll = l + k - 3;
        xv[k] = (ll >= 0)
            ? *(const float4*)(xz + ((size_t)b * LSEQ + ll) * (2 * DI) + e4)
            : make_float4(0.f, 0.f, 0.f, 0.f);
    }

    float4 acc = *(const float4*)(cb + e4);
    acc.x += w0.x * xv[0].x + w0.y * xv[1].x + w0.z * xv[2].x + w0.w * xv[3].x;
    acc.y += w1.x * xv[0].y + w1.y * xv[1].y + w1.z * xv[2].y + w1.w * xv[3].y;
    acc.z += w2.x * xv[0].z + w2.y * xv[1].z + w2.z * xv[2].z + w2.w * xv[3].z;
    acc.w += w3.x * xv[0].w + w3.y * xv[1].w + w3.z * xv[2].w + w3.w * xv[3].w;

    acc.x = acc.x / (1.f + __expf(-acc.x));
    acc.y = acc.y / (1.f + __expf(-acc.y));
    acc.z = acc.z / (1.f + __expf(-acc.z));
    acc.w = acc.w / (1.f + __expf(-acc.w));
    *(float4*)(xc + (size_t)bl * DI + e4) = acc;
}

// ================= chunked selective scan =================
__device__ __forceinline__ bool load_A(const float* __restrict__ A_log, int d, float* A) {
    bool structured = true;
#pragma unroll
    for (int n = 0; n < DS; n++) A[n] = -__expf(A_log[d * DS + n]);
#pragma unroll
    for (int n = 1; n < DS; n++) {
        float want = (n + 1) * A[0];
        structured &= fabsf(A[n] - want) <= 1e-4f * fabsf(want);
    }
    return structured;
}

__global__ __launch_bounds__(256) void scan_chunk_partial(
    const float* __restrict__ dt, const float* __restrict__ xc,
    const float* __restrict__ dbl, const float* __restrict__ A_log,
    float* __restrict__ Pout, float* __restrict__ Sout)
{
    __shared__ float sB[CS][DS];
    int d = blockIdx.x * 256 + threadIdx.x;
    int c = blockIdx.y;
    int b = blockIdx.z;
    int l0 = c * CS;

    for (int i = threadIdx.x; i < CS * DS; i += 256) {
        int s = i / DS, j = i % DS;
        sB[s][j] = dbl[((size_t)(b * LSEQ + l0 + s)) * XCOLS + DTR + j];
    }
    __syncthreads();

    float A[DS];
    bool structured = load_A(A_log, d, A);
    float A0 = A[0];

    float P[DS], S[DS];
#pragma unroll
    for (int n = 0; n < DS; n++) { P[n] = 1.f; S[n] = 0.f; }

    const float* dtp = dt + (size_t)(b * LSEQ + l0) * DI + d;
    const float* xcp = xc + (size_t)(b * LSEQ + l0) * DI + d;

    if (structured) {
        for (int s = 0; s < CS; s++) {
            float dtv = dtp[(size_t)s * DI];
            float xv  = xcp[(size_t)s * DI];
            float w = dtv * xv;
            float e1 = __expf(dtv * A0);
            float ee = 1.f;
#pragma unroll
            for (int n = 0; n < DS; n++) {
                ee *= e1;
                P[n] *= ee;
                S[n] = ee * S[n] + w * sB[s][n];
            }
        }
    } else {
        for (int s = 0; s < CS; s++) {
            float dtv = dtp[(size_t)s * DI];
            float xv  = xcp[(size_t)s * DI];
            float w = dtv * xv;
#pragma unroll
            for (int n = 0; n < DS; n++) {
                float ee = __expf(dtv * A[n]);
                P[n] *= ee;
                S[n] = ee * S[n] + w * sB[s][n];
            }
        }
    }

    size_t base = ((size_t)(b * NC + c) * DI + d) * DS;
#pragma unroll
    for (int n = 0; n < DS; n++) { Pout[base + n] = P[n]; Sout[base + n] = S[n]; }
}

__global__ __launch_bounds__(256) void scan_chunk_seq(
    const float* __restrict__ P, const float* __restrict__ S, float* __restrict__ h0)
{
    int idx = blockIdx.x * blockDim.x + threadIdx.x;
    if (idx >= BSZ * DI * DS) return;
    int b = idx / (DI * DS);
    int r = idx % (DI * DS);
    float h = 0.f;
    for (int c = 0; c < NC; c++) {
        size_t off = (size_t)b * NC * DI * DS + (size_t)c * DI * DS + r;
        h0[off] = h;
        h = P[off] * h + S[off];
    }
}

__global__ __launch_bounds__(256) void scan_chunk_final(
    const float* __restrict__ dt, const float* __restrict__ xc,
    const float* __restrict__ dbl, const float* __restrict__ xz,
    const float* __restrict__ A_log, const float* __restrict__ Dp,
    const float* __restrict__ h0, float* __restrict__ y)
{
    __shared__ float sBC[CS][2 * DS];
    int d = blockIdx.x * 256 + threadIdx.x;
    int c = blockIdx.y;
    int b = blockIdx.z;
    int l0 = c * CS;

    for (int i = threadIdx.x; i < CS * 2 * DS; i += 256) {
        int s = i / (2 * DS), j = i % (2 * DS);
        sBC[s][j] = dbl[((size_t)(b * LSEQ + l0 + s)) * XCOLS + DTR + j];
    }
    __syncthreads();

    float A[DS];
    bool structured = load_A(A_log, d, A);
    float A0 = A[0];
    float Dv = Dp[d];

    float h[DS];
    size_t hbase = ((size_t)(b * NC + c) * DI + d) * DS;
#pragma unroll
    for (int n = 0; n < DS; n++) h[n] = h0[hbase + n];

    const float* dtp = dt + (size_t)(b * LSEQ + l0) * DI + d;
    const float* xcp = xc + (size_t)(b * LSEQ + l0) * DI + d;
    const float* zp  = xz + (size_t)(b * LSEQ + l0) * 2 * DI + DI + d;
    float* yp = y + (size_t)(b * LSEQ + l0) * DI + d;

    if (structured) {
        for (int s = 0; s < CS; s++) {
            float dtv = dtp[(size_t)s * DI];
            float xv  = xcp[(size_t)s * DI];
            float w = dtv * xv;
            float e1 = __expf(dtv * A0);
            float ee = 1.f;
            float ya = 0.f;
#pragma unroll
            for (int n = 0; n < DS; n++) {
                ee *= e1;
                h[n] = ee * h[n] + w * sBC[s][n];
                ya += h[n] * sBC[s][DS + n];
            }
            float zv = zp[(size_t)s * 2 * DI];
            float sil = zv / (1.f + __expf(-zv));
            yp[(size_t)s * DI] = (ya + Dv * xv) * sil;
        }
    } else {
        for (int s = 0; s < CS; s++) {
            float dtv = dtp[(size_t)s * DI];
            float xv  = xcp[(size_t)s * DI];
            float w = dtv * xv;
            float ya = 0.f;
#pragma unroll
            for (int n = 0; n < DS; n++) {
                float ee = __expf(dtv * A[n]);
                h[n] = ee * h[n] + w * sBC[s][n];
                ya += h[n] * sBC[s][DS + n];
            }
            float zv = zp[(size_t)s * 2 * DI];
            float sil = zv / (1.f + __expf(-zv));
            yp[(size_t)s * DI] = (ya + Dv * xv) * sil;
        }
    }
}

// ---------------- fused max-pool + classifier head ----------------
__global__ void poolhead_k(const float* __restrict__ h, const float* __restrict__ hw,
                           const float* __restrict__ hb, float* __restrict__ out)
{
    int n = blockIdx.x;        // 0..31
    int t = threadIdx.x;       // 0..383
    const float* base = h + (size_t)n * 196 * DM + t;
    float m = -1e30f;
    for (int p = 0; p < 196; p++) m = fmaxf(m, base[(size_t)p * DM]);
    __shared__ float sp[DM];
    sp[t] = m;
    __syncthreads();
    if (t < 96) {
        int c = t / 32, lane = t % 32;
        float acc = 0.f;
        for (int k = lane; k < DM; k += 32) acc += sp[k] * hw[c * DM + k];
#pragma unroll
        for (int o = 16; o; o >>= 1) acc += __shfl_xor_sync(0xffffffffu, acc, o);
        if (lane == 0) out[n * 3 + c] = acc + hb[c];
    }
}

// ---------------- host orchestration ----------------
static void mma_call(const float* A, int lda, const bf16* Wh, const bf16* Wl,
                     int N, int K, float* C, int ldc,
                     const float* bias, const float* res, int act, int nReal)
{
    dim3 grid(N / 64, NROW / 128);
    mma_gemm<<<grid, 256, MG_SMEM>>>(A, lda, Wh, Wl, K, C, ldc,
                                     bias, res, K, act, nReal);
}

extern "C" void kernel_launch(void* const* d_in, const int* in_sizes, int n_in,
                              void* d_out, int out_size)
{
    const float* x       = (const float*)d_in[0];
    const float* patch_w = (const float*)d_in[1];
    const float* patch_b = (const float*)d_in[2];
    const float* ln1_g   = (const float*)d_in[3];
    const float* ln1_b   = (const float*)d_in[4];
    const float* in_w    = (const float*)d_in[5];
    const float* conv_w  = (const float*)d_in[6];
    const float* conv_b  = (const float*)d_in[7];
    const float* xproj_w = (const float*)d_in[8];
    const float* dt_w    = (const float*)d_in[9];
    const float* dt_b    = (const float*)d_in[10];
    const float* A_log   = (const float*)d_in[11];
    const float* Dparam  = (const float*)d_in[12];
    const float* out_w   = (const float*)d_in[13];
    const float* ln2_g   = (const float*)d_in[14];
    const float* ln2_b   = (const float*)d_in[15];
    const float* fc1_w   = (const float*)d_in[16];
    const float* fc1_b   = (const float*)d_in[17];
    const float* fc2_w   = (const float*)d_in[18];
    const float* fc2_b   = (const float*)d_in[19];
    const float* head_w  = (const float*)d_in[20];
    const float* head_b  = (const float*)d_in[21];
    float* out = (float*)d_out;

    cudaFuncSetAttribute(mma_gemm, cudaFuncAttributeMaxDynamicSharedMemorySize, MG_SMEM);

    float *xf, *h, *ln, *xz, *xc, *dbl, *dt, *y, *m1, *P, *S, *h0;
    bf16 *wh, *wl;
    cudaGetSymbolAddress((void**)&xf,  g_xf);
    cudaGetSymbolAddress((void**)&h,   g_h);
    cudaGetSymbolAddress((void**)&ln,  g_ln);
    cudaGetSymbolAddress((void**)&xz,  g_xz);
    cudaGetSymbolAddress((void**)&xc,  g_xc);
    cudaGetSymbolAddress((void**)&dbl, g_dbl);
    cudaGetSymbolAddress((void**)&dt,  g_dt);
    cudaGetSymbolAddress((void**)&y,   g_y);
    cudaGetSymbolAddress((void**)&m1,  g_m1);
    cudaGetSymbolAddress((void**)&P,   g_P);
    cudaGetSymbolAddress((void**)&S,   g_S);
    cudaGetSymbolAddress((void**)&h0,  g_h0);
    cudaGetSymbolAddress((void**)&wh,  g_wh);
    cudaGetSymbolAddress((void**)&wl,  g_wl);

    // --- convert all weights upfront (6 launches; overlaps patchify) ---
    wcvt_k<<<296, 256>>>(patch_w, wh + WOFF_PATCH, wl + WOFF_PATCH, WSZ_PATCH);
    wcvt_k<<<592, 256>>>(in_w,  wh + WOFF_INW,  wl + WOFF_INW,  4 * WSZ_INW);
    wcvt_k<<<592, 256>>>(out_w, wh + WOFF_OUTW, wl + WOFF_OUTW, 4 * WSZ_OUTW);
    wcvt_k<<<592, 256>>>(fc1_w, wh + WOFF_FC1,  wl + WOFF_FC1,  4 * WSZ_FC1);
    wcvt_k<<<592, 256>>>(fc2_w, wh + WOFF_FC2,  wl + WOFF_FC2,  4 * WSZ_FC2);
    wcvt_xpj_k<<<(4 * WSZ_XPJ + 255) / 256, 256>>>(xproj_w, wh + WOFF_XPJ, wl + WOFF_XPJ);

    // patchify + patch embed -> h
    gather_patches_k<<<(NROW * DI + 255) / 256, 256>>>(x, xf);
    mma_call(xf, DI, wh + WOFF_PATCH, wl + WOFF_PATCH, DM, DI,
             h, DM, patch_b, nullptr, 0, DM);

    for (int i = 0; i < 4; i++) {
        const bf16* inwh = wh + WOFF_INW + (size_t)i * WSZ_INW;
        const bf16* inwl = wl + WOFF_INW + (size_t)i * WSZ_INW;
        const bf16* owh  = wh + WOFF_OUTW + (size_t)i * WSZ_OUTW;
        const bf16* owl  = wl + WOFF_OUTW + (size_t)i * WSZ_OUTW;
        const bf16* f1h  = wh + WOFF_FC1 + (size_t)i * WSZ_FC1;
        const bf16* f1l  = wl + WOFF_FC1 + (size_t)i * WSZ_FC1;
        const bf16* f2h  = wh + WOFF_FC2 + (size_t)i * WSZ_FC2;
        const bf16* f2l  = wl + WOFF_FC2 + (size_t)i * WSZ_FC2;
        const bf16* xph  = wh + WOFF_XPJ + (size_t)i * WSZ_XPJ;
        const bf16* xpl  = wl + WOFF_XPJ + (size_t)i * WSZ_XPJ;

        // --- mamba block ---
        layernorm_k<<<NROW, 128>>>(h, ln1_g + i * DM, ln1_b + i * DM, ln);
        mma_call(ln, DM, inwh, inwl, 2 * DI, DM,
                 xz, 2 * DI, nullptr, nullptr, 0, 2 * DI);
        conv_silu_k<<<(NROW * DI / 4 + 255) / 256, 256>>>(
            xz, conv_w + (size_t)i * DI * 4, conv_b + (size_t)i * DI, xc);
        // xproj on tensor cores (padded N=64, real 52)
        mma_call(xc, DI, xph, xpl, XPAD, DI,
                 dbl, XCOLS, nullptr, nullptr, 0, XCOLS);
        {
            dim3 grid((DI + TBN - 1) / TBN, NROW / TBM);
            sgemm128<<<grid, 256>>>(dbl, XCOLS, dt_w + (size_t)i * DI * DTR, DTR,
                                    dt, DI, dt_b + (size_t)i * DI, nullptr,
                                    DI, DTR, 1 /*softplus*/);
        }

        // --- chunked selective scan ---
        {
            dim3 gA(DI / 256, NC, BSZ);
            scan_chunk_partial<<<gA, 256>>>(dt, xc, dbl,
                                            A_log + (size_t)i * DI * DS, P, S);
            scan_chunk_seq<<<(BSZ * DI * DS + 255) / 256, 256>>>(P, S, h0);
            scan_chunk_final<<<gA, 256>>>(dt, xc, dbl, xz,
                                          A_log + (size_t)i * DI * DS,
                                          Dparam + (size_t)i * DI, h0, y);
        }

        mma_call(y, DI, owh, owl, DM, DI,
                 h, DM, nullptr, h /*residual*/, 0, DM);

        // --- mlp block ---
        layernorm_k<<<NROW, 128>>>(h, ln2_g + i * DM, ln2_b + i * DM, ln);
        mma_call(ln, DM, f1h, f1l, DHID, DM,
                 m1, DHID, fc1_b + (size_t)i * DHID, nullptr, 2 /*gelu*/, DHID);
        mma_call(m1, DHID, f2h, f2l, DM, DHID,
                 h, DM, fc2_b + (size_t)i * DM, h /*residual*/, 0, DM);
    }

    poolhead_k<<<32, DM>>>(h, head_w, head_b, out);
}

// round 16
// speedup vs baseline: 1.0681x; 1.0248x over previous
#include <cuda_runtime.h>
#include <cuda_bf16.h>
#include <cstdint>
#include <cstdio>

// ---------------- problem constants ----------------
#define BSZ    2
#define TT     16
#define LSEQ   3136          // TT * 196
#define NROW   6272          // BSZ * LSEQ (== 49*128)
#define DM     384
#define DI     768
#define DS     14
#define DTR    24
#define XCOLS  52            // DTR + 2*DS
#define XPAD   64            // xproj weight padded rows
#define DHID   1536          // 4*DM == 2*DI

// chunked scan
#define NC     56
#define CS     56

typedef __nv_bfloat16 bf16;

// weight arena offsets (elements)
#define WOFF_PATCH 0
#define WSZ_PATCH  (DM * DI)
#define WOFF_INW   (WOFF_PATCH + WSZ_PATCH)
#define WSZ_INW    (2 * DI * DM)
#define WOFF_OUTW  (WOFF_INW + 4 * WSZ_INW)
#define WSZ_OUTW   (DM * DI)
#define WOFF_FC1   (WOFF_OUTW + 4 * WSZ_OUTW)
#define WSZ_FC1    (DHID * DM)
#define WOFF_FC2   (WOFF_FC1 + 4 * WSZ_FC1)
#define WSZ_FC2    (DM * DHID)
#define WOFF_XPJ   (WOFF_FC2 + 4 * WSZ_FC2)
#define WSZ_XPJ    (XPAD * DI)                 // padded 64x768 per layer
#define WARENA     (WOFF_XPJ + 4 * WSZ_XPJ)

// ---------------- scratch ----------------
__device__ float g_xf [NROW * DI];
__device__ float g_h  [NROW * DM];
__device__ float g_ln [NROW * DM];
__device__ float g_xz [NROW * 2 * DI];
__device__ float g_xc [NROW * DI];
__device__ float g_dbl[NROW * XCOLS];
__device__ float g_dt [NROW * DI];
__device__ float g_y  [NROW * DI];
__device__ float g_m1 [NROW * DHID];
__device__ float g_P  [BSZ * NC * DI * DS];
__device__ float g_S  [BSZ * NC * DI * DS];
__device__ float g_h0 [BSZ * NC * DI * DS];
// persistent hi/lo weight arena (all layers)
__device__ __align__(16) bf16 g_wh[WARENA];
__device__ __align__(16) bf16 g_wl[WARENA];

// ---------------- activations ----------------
__device__ __forceinline__ float softplus_f(float x) {
    return fmaxf(x, 0.f) + log1pf(expf(-fabsf(x)));
}
__device__ __forceinline__ float gelu_f(float x) {
    float x3 = x * x * x;
    float t = tanhf(0.7978845608028654f * (x + 0.044715f * x3));
    return 0.5f * x * (1.f + t);
}

__device__ __forceinline__ uint32_t smem_u32(const void* p) {
    uint32_t a;
    asm("{ .reg .u64 t; cvta.to.shared.u64 t, %1; cvt.u32.u64 %0, t; }" : "=r"(a) : "l"(p));
    return a;
}

__device__ __forceinline__ void split_bf16(float v, bf16& hi, bf16& lo) {
    hi = __float2bfloat16(v);
    lo = __float2bfloat16(v - __bfloat162float(hi));
}

// ================= bf16-split tensor-core GEMM (mma.sync) =================
// C[M,N] = act(A[M,K]*W^T + bias) + res.  A fp32 (split in-kernel);
// W pre-split bf16 hi/lo from the arena.  M%128==0, N%64==0, K%32==0.
// Warp tile 32x32 (8 warps as 4x2).
#define KB 32
#define SROW 40
#define MG_AH 0
#define MG_AL 10240
#define MG_WH 20480
#define MG_WL 25600
#define MG_STAGE 30720
#define MG_SMEM (2 * MG_STAGE)

__device__ __forceinline__ void ldm_x4(uint32_t& r0, uint32_t& r1, uint32_t& r2,
                                       uint32_t& r3, uint32_t addr) {
    asm volatile("ldmatrix.sync.aligned.m8n8.x4.shared.b16 {%0,%1,%2,%3}, [%4];"
                 : "=r"(r0), "=r"(r1), "=r"(r2), "=r"(r3) : "r"(addr));
}
__device__ __forceinline__ void mma_bf16(float* d, const uint32_t* a,
                                         uint32_t b0, uint32_t b1) {
    asm volatile(
        "mma.sync.aligned.m16n8k16.row.col.f32.bf16.bf16.f32 "
        "{%0,%1,%2,%3}, {%4,%5,%6,%7}, {%8,%9}, {%0,%1,%2,%3};"
        : "+f"(d[0]), "+f"(d[1]), "+f"(d[2]), "+f"(d[3])
        : "r"(a[0]), "r"(a[1]), "r"(a[2]), "r"(a[3]), "r"(b0), "r"(b1));
}

__device__ __forceinline__ void cvt_split4(float4 v, uint16_t* hi, uint16_t* lo) {
    __nv_bfloat16 hx = __float2bfloat16(v.x), hy = __float2bfloat16(v.y);
    __nv_bfloat16 hz = __float2bfloat16(v.z), hw = __float2bfloat16(v.w);
    __nv_bfloat16 gx = __float2bfloat16(v.x - __bfloat162float(hx));
    __nv_bfloat16 gy = __float2bfloat16(v.y - __bfloat162float(hy));
    __nv_bfloat16 gz = __float2bfloat16(v.z - __bfloat162float(hz));
    __nv_bfloat16 gw = __float2bfloat16(v.w - __bfloat162float(hw));
    uint2 hp, lp;
    hp.x = (uint32_t)__bfloat16_as_ushort(hy) << 16 | __bfloat16_as_ushort(hx);
    hp.y = (uint32_t)__bfloat16_as_ushort(hw) << 16 | __bfloat16_as_ushort(hz);
    lp.x = (uint32_t)__bfloat16_as_ushort(gy) << 16 | __bfloat16_as_ushort(gx);
    lp.y = (uint32_t)__bfloat16_as_ushort(gw) << 16 | __bfloat16_as_ushort(gz);
    *(uint2*)hi = hp;
    *(uint2*)lo = lp;
}

__global__ __launch_bounds__(256, 2) void mma_gemm(
    const float* __restrict__ A, int lda,
    const bf16* __restrict__ Wh, const bf16* __restrict__ Wl, int ldw,
    float* __restrict__ C, int ldc,
    const float* __restrict__ bias,
    const float* __restrict__ res,
    int K, int act, int nReal)
{
    extern __shared__ __align__(16) char dsm[];

    int tid  = threadIdx.x;
    int wid  = tid >> 5;
    int lane = tid & 31;
    int bm0 = blockIdx.y * 128;
    int bn0 = blockIdx.x * 64;
    int wm = (wid >> 1) * 32;   // 0/32/64/96
    int wn = (wid & 1) * 32;    // 0/32

    float acc[2][4][4];
#pragma unroll
    for (int mt = 0; mt < 2; mt++)
#pragma unroll
        for (int nt = 0; nt < 4; nt++)
#pragma unroll
            for (int i = 0; i < 4; i++) acc[mt][nt][i] = 0.f;

    int lrA[4], lcA[4];
#pragma unroll
    for (int i = 0; i < 4; i++) {
        int idx = i * 256 + tid;
        lrA[i] = idx >> 3;
        lcA[i] = (idx & 7) * 4;
    }
    int wr = tid >> 2, wc = (tid & 3) * 8;
    uint32_t oW = (uint32_t)(wr * SROW + wc) * 2;

    const bf16* gWh = Wh + (size_t)(bn0 + wr) * ldw + wc;
    const bf16* gWl = Wl + (size_t)(bn0 + wr) * ldw + wc;

    float4 pa[4];
    uint4 pwh, pwl;
#pragma unroll
    for (int i = 0; i < 4; i++)
        pa[i] = *(const float4*)(A + (size_t)(bm0 + lrA[i]) * lda + lcA[i]);
    pwh = *(const uint4*)gWh;
    pwl = *(const uint4*)gWl;

    {
        char* sn = dsm;
#pragma unroll
        for (int i = 0; i < 4; i++) {
            int o = lrA[i] * SROW + lcA[i];
            cvt_split4(pa[i], (uint16_t*)(sn + MG_AH) + o, (uint16_t*)(sn + MG_AL) + o);
        }
        *(uint4*)(sn + MG_WH + oW) = pwh;
        *(uint4*)(sn + MG_WL + oW) = pwl;
    }
    __syncthreads();

    uint32_t sAh[2], sAl[2], sWh[2], sWl[2];
#pragma unroll
    for (int s = 0; s < 2; s++) {
        sAh[s] = smem_u32(dsm + s * MG_STAGE + MG_AH);
        sAl[s] = smem_u32(dsm + s * MG_STAGE + MG_AL);
        sWh[s] = smem_u32(dsm + s * MG_STAGE + MG_WH);
        sWl[s] = smem_u32(dsm + s * MG_STAGE + MG_WL);
    }

    int frow = lane & 15;
    int fk   = (lane >> 4) << 3;

    int nch = K / KB;
    for (int c = 0; c < nch; c++) {
        int cur = c & 1, nxt = cur ^ 1;

        if (c + 1 < nch) {
            int ko = (c + 1) * KB;
#pragma unroll
            for (int i = 0; i < 4; i++)
                pa[i] = *(const float4*)(A + (size_t)(bm0 + lrA[i]) * lda + ko + lcA[i]);
            pwh = *(const uint4*)(gWh + ko);
            pwl = *(const uint4*)(gWl + ko);
        }

#pragma unroll
        for (int k0 = 0; k0 < KB; k0 += 16) {
            // W fragments: 32 cols of this warp, hi and lo (4 ldmatrix)
            uint32_t bh[4][2], bl[4][2];
#pragma unroll
            for (int nh = 0; nh < 2; nh++) {
                uint32_t off = (uint32_t)((wn + nh * 16 + frow) * SROW + k0 + fk) * 2;
                uint32_t r0, r1, r2, r3;
                ldm_x4(r0, r1, r2, r3, sWh[cur] + off);
                bh[nh * 2 + 0][0] = r0; bh[nh * 2 + 0][1] = r2;
                bh[nh * 2 + 1][0] = r1; bh[nh * 2 + 1][1] = r3;
                ldm_x4(r0, r1, r2, r3, sWl[cur] + off);
                bl[nh * 2 + 0][0] = r0; bl[nh * 2 + 0][1] = r2;
                bl[nh * 2 + 1][0] = r1; bl[nh * 2 + 1][1] = r3;
            }
            // A fragments: 32 rows, hi and lo (4 ldmatrix), then 24 MMA
#pragma unroll
            for (int mt = 0; mt < 2; mt++) {
                uint32_t off = (uint32_t)((wm + mt * 16 + frow) * SROW + k0 + fk) * 2;
                uint32_t ah[4], al[4];
                ldm_x4(ah[0], ah[1], ah[2], ah[3], sAh[cur] + off);
                ldm_x4(al[0], al[1], al[2], al[3], sAl[cur] + off);
#pragma unroll
                for (int nt = 0; nt < 4; nt++) {
                    mma_bf16(acc[mt][nt], ah, bh[nt][0], bh[nt][1]);
                    mma_bf16(acc[mt][nt], ah, bl[nt][0], bl[nt][1]);
                    mma_bf16(acc[mt][nt], al, bh[nt][0], bh[nt][1]);
                }
            }
        }

        if (c + 1 < nch) {
            char* sn = dsm + nxt * MG_STAGE;
#pragma unroll
            for (int i = 0; i < 4; i++) {
                int o = lrA[i] * SROW + lcA[i];
                cvt_split4(pa[i], (uint16_t*)(sn + MG_AH) + o, (uint16_t*)(sn + MG_AL) + o);
            }
            *(uint4*)(sn + MG_WH + oW) = pwh;
            *(uint4*)(sn + MG_WL + oW) = pwl;
            __syncthreads();
        }
    }

    // epilogue: fragment row = lane/4 (+8), col = (lane%4)*2 (+1)
    int gq = lane >> 2;
    int gr = (lane & 3) * 2;
#pragma unroll
    for (int mt = 0; mt < 2; mt++) {
#pragma unroll
        for (int half = 0; half < 2; half++) {
            int gm = bm0 + wm + mt * 16 + gq + half * 8;
            float* crow = C + (size_t)gm * ldc;
            const float* rrow = res ? res + (size_t)gm * ldc : nullptr;
#pragma unroll
            for (int nt = 0; nt < 4; nt++) {
                int gn = bn0 + wn + nt * 8 + gr;
                if (gn >= nReal) continue;
                float v0 = acc[mt][nt][half * 2 + 0];
                float v1 = acc[mt][nt][half * 2 + 1];
                if (bias) { v0 += bias[gn]; v1 += bias[gn + 1]; }
                if (act == 2)      { v0 = gelu_f(v0);     v1 = gelu_f(v1); }
                else if (act == 1) { v0 = softplus_f(v0); v1 = softplus_f(v1); }
                if (rrow) { v0 += rrow[gn]; v1 += rrow[gn + 1]; }
                *(float2*)(crow + gn) = make_float2(v0, v1);
            }
        }
    }
}

// ---------------- ALL weights fp32 -> bf16 hi/lo in ONE launch ----------------
__global__ void wcvt_all_k(const float* __restrict__ patch_w,
                           const float* __restrict__ in_w,
                           const float* __restrict__ out_w,
                           const float* __restrict__ fc1_w,
                           const float* __restrict__ fc2_w,
                           const float* __restrict__ xproj_w,
                           bf16* __restrict__ hi, bf16* __restrict__ lo)
{
    for (int i = blockIdx.x * 256 + threadIdx.x; i < WARENA; i += gridDim.x * 256) {
        float v;
        if (i < WOFF_INW) {
            v = patch_w[i - WOFF_PATCH];
        } else if (i < WOFF_OUTW) {
            v = in_w[i - WOFF_INW];
        } else if (i < WOFF_FC1) {
            v = out_w[i - WOFF_OUTW];
        } else if (i < WOFF_FC2) {
            v = fc1_w[i - WOFF_FC1];
        } else if (i < WOFF_XPJ) {
            v = fc2_w[i - WOFF_FC2];
        } else {
            int rem   = i - WOFF_XPJ;
            int layer = rem / (XPAD * DI);
            int r2    = rem % (XPAD * DI);
            int row   = r2 / DI;
            int col   = r2 % DI;
            v = (row < XCOLS) ? xproj_w[((size_t)layer * XCOLS + row) * DI + col] : 0.f;
        }
        bf16 h, l;
        split_bf16(v, h, l);
        hi[i] = h; lo[i] = l;
    }
}

// ---------------- patchify gather (float4 vectorized) ----------------
// thread handles 4 consecutive px -> contiguous in both src and dst
__global__ void gather_patches_k(const float* __restrict__ x, float* __restrict__ xf) {
    int idx = blockIdx.x * blockDim.x + threadIdx.x;
    if (idx >= NROW * DI / 4) return;
    int c4  = (idx % (DI / 4)) * 4;      // col0 (multiple of 4)
    int row = idx / (DI / 4);
    int n  = row / 196, p = row % 196;
    int ph = p / 14,   pw = p % 14;
    int ch = c4 >> 8;
    int rem = c4 & 255;
    int py = rem >> 4, px = rem & 15;    // px multiple of 4
    float4 v = *(const float4*)(x + ((size_t)(n * 3 + ch) * 224 + (ph * 16 + py)) * 224
                                + (pw * 16 + px));
    *(float4*)(xf + (size_t)row * DI + c4) = v;
}

// ================= FFMA 128x128 double-buffered SGEMM (K%8==0, for dt) ===========
#define TBM 128
#define TBN 128
#define TBK 8
__global__ __launch_bounds__(256, 2) void sgemm128(
    const float* __restrict__ A, int lda,
    const float* __restrict__ W, int ldw,
    float* __restrict__ C, int ldc,
    const float* __restrict__ bias,
    const float* __restrict__ res,
    int N, int K, int act)
{
    __shared__ __align__(16) float As[2][TBK][TBM];
    __shared__ __align__(16) float Ws[2][TBK][TBN];

    int bm0 = blockIdx.y * TBM;
    int bn0 = blockIdx.x * TBN;
    int tid = threadIdx.x;
    int tm = tid >> 4;
    int tn = tid & 15;
    int lr = tid >> 1;
    int lk = (tid & 1) * 4;

    const float* Aptr = A + (size_t)(bm0 + lr) * lda + lk;
    bool wok = (bn0 + lr) < N;
    const float* Wptr = W + (size_t)(wok ? (bn0 + lr) : 0) * ldw + lk;

    float4 av = *(const float4*)Aptr;
    float4 wv = wok ? *(const float4*)Wptr : make_float4(0.f, 0.f, 0.f, 0.f);
    As[0][lk + 0][lr] = av.x; As[0][lk + 1][lr] = av.y;
    As[0][lk + 2][lr] = av.z; As[0][lk + 3][lr] = av.w;
    Ws[0][lk + 0][lr] = wv.x; Ws[0][lk + 1][lr] = wv.y;
    Ws[0][lk + 2][lr] = wv.z; Ws[0][lk + 3][lr] = wv.w;
    __syncthreads();

    float acc[8][8];
#pragma unroll
    for (int i = 0; i < 8; i++)
#pragma unroll
        for (int j = 0; j < 8; j++) acc[i][j] = 0.f;

    int nk = K / TBK;
    for (int kt = 0; kt < nk; kt++) {
        int cur = kt & 1, nxt = cur ^ 1;
        if (kt + 1 < nk) {
            av = *(const float4*)(Aptr + (size_t)(kt + 1) * TBK);
            wv = wok ? *(const float4*)(Wptr + (size_t)(kt + 1) * TBK)
                     : make_float4(0.f, 0.f, 0.f, 0.f);
        }
#pragma unroll
        for (int kk = 0; kk < TBK; kk++) {
            float4 a0 = *(const float4*)&As[cur][kk][tm * 4];
            float4 a1 = *(const float4*)&As[cur][kk][tm * 4 + 64];
            float4 w0 = *(const float4*)&Ws[cur][kk][tn * 4];
            float4 w1 = *(const float4*)&Ws[cur][kk][tn * 4 + 64];
            float a[8] = {a0.x, a0.y, a0.z, a0.w, a1.x, a1.y, a1.z, a1.w};
            float w[8] = {w0.x, w0.y, w0.z, w0.w, w1.x, w1.y, w1.z, w1.w};
#pragma unroll
            for (int i = 0; i < 8; i++)
#pragma unroll
                for (int j = 0; j < 8; j++)
                    acc[i][j] = fmaf(a[i], w[j], acc[i][j]);
        }
        if (kt + 1 < nk) {
            As[nxt][lk + 0][lr] = av.x; As[nxt][lk + 1][lr] = av.y;
            As[nxt][lk + 2][lr] = av.z; As[nxt][lk + 3][lr] = av.w;
            Ws[nxt][lk + 0][lr] = wv.x; Ws[nxt][lk + 1][lr] = wv.y;
            Ws[nxt][lk + 2][lr] = wv.z; Ws[nxt][lk + 3][lr] = wv.w;
            __syncthreads();
        }
    }

#pragma unroll
    for (int ih = 0; ih < 2; ih++)
#pragma unroll
    for (int i = 0; i < 4; i++) {
        int gm = bm0 + tm * 4 + ih * 64 + i;
#pragma unroll
        for (int jh = 0; jh < 2; jh++)
#pragma unroll
        for (int j = 0; j < 4; j++) {
            int gn = bn0 + tn * 4 + jh * 64 + j;
            if (gn >= N) continue;
            float v = acc[ih * 4 + i][jh * 4 + j];
            if (bias) v += bias[gn];
            if (act == 1) v = softplus_f(v);
            else if (act == 2) v = gelu_f(v);
            if (res) v += res[(size_t)gm * ldc + gn];
            C[(size_t)gm * ldc + gn] = v;
        }
    }
}

// ---------------- layernorm ----------------
__global__ void layernorm_k(const float* __restrict__ x, const float* __restrict__ g,
                            const float* __restrict__ b, float* __restrict__ out)
{
    int row = blockIdx.x;
    int t = threadIdx.x;
    const float* xr = x + (size_t)row * DM;
    float v0 = xr[t], v1 = xr[t + 128], v2 = xr[t + 256];
    float s  = v0 + v1 + v2;
    float s2 = v0 * v0 + v1 * v1 + v2 * v2;
#pragma unroll
    for (int o = 16; o; o >>= 1) {
        s  += __shfl_xor_sync(0xffffffffu, s,  o);
        s2 += __shfl_xor_sync(0xffffffffu, s2, o);
    }
    __shared__ float ss[4], ss2[4];
    int w = t >> 5;
    if ((t & 31) == 0) { ss[w] = s; ss2[w] = s2; }
    __syncthreads();
    s  = ss[0] + ss[1] + ss[2] + ss[3];
    s2 = ss2[0] + ss2[1] + ss2[2] + ss2[3];
    float mu  = s * (1.f / DM);
    float var = s2 * (1.f / DM) - mu * mu;
    float r = rsqrtf(var + 1e-5f);
    float* orow = out + (size_t)row * DM;
    orow[t]       = (v0 - mu) * r * g[t]       + b[t];
    orow[t + 128] = (v1 - mu) * r * g[t + 128] + b[t + 128];
    orow[t + 256] = (v2 - mu) * r * g[t + 256] + b[t + 256];
}

// ---------------- causal conv1d (width 4) + silu, vectorized ----------------
__global__ void conv_silu_k(const float* __restrict__ xz, const float* __restrict__ cw,
                            const float* __restrict__ cb, float* __restrict__ xc)
{
    int idx = blockIdx.x * blockDim.x + threadIdx.x;
    if (idx >= NROW * DI / 4) return;
    int e4 = (idx % (DI / 4)) * 4;
    int bl = idx / (DI / 4);
    int b = bl / LSEQ, l = bl % LSEQ;

    float4 w0 = *(const float4*)(cw + (e4 + 0) * 4);
    float4 w1 = *(const float4*)(cw + (e4 + 1) * 4);
    float4 w2 = *(const float4*)(cw + (e4 + 2) * 4);
    float4 w3 = *(const float4*)(cw + (e4 + 3) * 4);

    float4 xv[4];
#pragma unroll
    for (int k = 0; k < 4; k++) {
        int ll = l + k - 3;
        xv[k] = (ll >= 0)
            ? *(const float4*)(xz + ((size_t)b * LSEQ + ll) * (2 * DI) + e4)
            : make_float4(0.f, 0.f, 0.f, 0.f);
    }

    float4 acc = *(const float4*)(cb + e4);
    acc.x += w0.x * xv[0].x + w0.y * xv[1].x + w0.z * xv[2].x + w0.w * xv[3].x;
    acc.y += w1.x * xv[0].y + w1.y * xv[1].y + w1.z * xv[2].y + w1.w * xv[3].y;
    acc.z += w2.x * xv[0].z + w2.y * xv[1].z + w2.z * xv[2].z + w2.w * xv[3].z;
    acc.w += w3.x * xv[0].w + w3.y * xv[1].w + w3.z * xv[2].w + w3.w * xv[3].w;

    acc.x = acc.x / (1.f + __expf(-acc.x));
    acc.y = acc.y / (1.f + __expf(-acc.y));
    acc.z = acc.z / (1.f + __expf(-acc.z));
    acc.w = acc.w / (1.f + __expf(-acc.w));
    *(float4*)(xc + (size_t)bl * DI + e4) = acc;
}

// ================= chunked selective scan =================
__device__ __forceinline__ bool load_A(const float* __restrict__ A_log, int d, float* A) {
    bool structured = true;
#pragma unroll
    for (int n = 0; n < DS; n++) A[n] = -__expf(A_log[d * DS + n]);
#pragma unroll
    for (int n = 1; n < DS; n++) {
        float want = (n + 1) * A[0];
        structured &= fabsf(A[n] - want) <= 1e-4f * fabsf(want);
    }
    return structured;
}

__global__ __launch_bounds__(256) void scan_chunk_partial(
    const float* __restrict__ dt, const float* __restrict__ xc,
    const float* __restrict__ dbl, const float* __restrict__ A_log,
    float* __restrict__ Pout, float* __restrict__ Sout)
{
    __shared__ float sB[CS][DS];
    int d = blockIdx.x * 256 + threadIdx.x;
    int c = blockIdx.y;
    int b = blockIdx.z;
    int l0 = c * CS;

    for (int i = threadIdx.x; i < CS * DS; i += 256) {
        int s = i / DS, j = i % DS;
        sB[s][j] = dbl[((size_t)(b * LSEQ + l0 + s)) * XCOLS + DTR + j];
    }
    __syncthreads();

    float A[DS];
    bool structured = load_A(A_log, d, A);
    float A0 = A[0];

    float P[DS], S[DS];
#pragma unroll
    for (int n = 0; n < DS; n++) { P[n] = 1.f; S[n] = 0.f; }

    const float* dtp = dt + (size_t)(b * LSEQ + l0) * DI + d;
    const float* xcp = xc + (size_t)(b * LSEQ + l0) * DI + d;

    if (structured) {
        for (int s = 0; s < CS; s++) {
            float dtv = dtp[(size_t)s * DI];
            float xv  = xcp[(size_t)s * DI];
            float w = dtv * xv;
            float e1 = __expf(dtv * A0);
            float ee = 1.f;
#pragma unroll
            for (int n = 0; n < DS; n++) {
                ee *= e1;
                P[n] *= ee;
                S[n] = ee * S[n] + w * sB[s][n];
            }
        }
    } else {
        for (int s = 0; s < CS; s++) {
            float dtv = dtp[(size_t)s * DI];
            float xv  = xcp[(size_t)s * DI];
            float w = dtv * xv;
#pragma unroll
            for (int n = 0; n < DS; n++) {
                float ee = __expf(dtv * A[n]);
                P[n] *= ee;
                S[n] = ee * S[n] + w * sB[s][n];
            }
        }
    }

    size_t base = ((size_t)(b * NC + c) * DI + d) * DS;
#pragma unroll
    for (int n = 0; n < DS; n++) { Pout[base + n] = P[n]; Sout[base + n] = S[n]; }
}

__global__ __launch_bounds__(256) void scan_chunk_seq(
    const float* __restrict__ P, const float* __restrict__ S, float* __restrict__ h0)
{
    int idx = blockIdx.x * blockDim.x + threadIdx.x;
    if (idx >= BSZ * DI * DS) return;
    int b = idx / (DI * DS);
    int r = idx % (DI * DS);
    float h = 0.f;
    for (int c = 0; c < NC; c++) {
        size_t off = (size_t)b * NC * DI * DS + (size_t)c * DI * DS + r;
        h0[off] = h;
        h = P[off] * h + S[off];
    }
}

__global__ __launch_bounds__(256) void scan_chunk_final(
    const float* __restrict__ dt, const float* __restrict__ xc,
    const float* __restrict__ dbl, const float* __restrict__ xz,
    const float* __restrict__ A_log, const float* __restrict__ Dp,
    const float* __restrict__ h0, float* __restrict__ y)
{
    __shared__ float sBC[CS][2 * DS];
    int d = blockIdx.x * 256 + threadIdx.x;
    int c = blockIdx.y;
    int b = blockIdx.z;
    int l0 = c * CS;

    for (int i = threadIdx.x; i < CS * 2 * DS; i += 256) {
        int s = i / (2 * DS), j = i % (2 * DS);
        sBC[s][j] = dbl[((size_t)(b * LSEQ + l0 + s)) * XCOLS + DTR + j];
    }
    __syncthreads();

    float A[DS];
    bool structured = load_A(A_log, d, A);
    float A0 = A[0];
    float Dv = Dp[d];

    float h[DS];
    size_t hbase = ((size_t)(b * NC + c) * DI + d) * DS;
#pragma unroll
    for (int n = 0; n < DS; n++) h[n] = h0[hbase + n];

    const float* dtp = dt + (size_t)(b * LSEQ + l0) * DI + d;
    const float* xcp = xc + (size_t)(b * LSEQ + l0) * DI + d;
    const float* zp  = xz + (size_t)(b * LSEQ + l0) * 2 * DI + DI + d;
    float* yp = y + (size_t)(b * LSEQ + l0) * DI + d;

    if (structured) {
        for (int s = 0; s < CS; s++) {
            float dtv = dtp[(size_t)s * DI];
            float xv  = xcp[(size_t)s * DI];
            float w = dtv * xv;
            float e1 = __expf(dtv * A0);
            float ee = 1.f;
            float ya = 0.f;
#pragma unroll
            for (int n = 0; n < DS; n++) {
                ee *= e1;
                h[n] = ee * h[n] + w * sBC[s][n];
                ya += h[n] * sBC[s][DS + n];
            }
            float zv = zp[(size_t)s * 2 * DI];
            float sil = zv / (1.f + __expf(-zv));
            yp[(size_t)s * DI] = (ya + Dv * xv) * sil;
        }
    } else {
        for (int s = 0; s < CS; s++) {
            float dtv = dtp[(size_t)s * DI];
            float xv  = xcp[(size_t)s * DI];
            float w = dtv * xv;
            float ya = 0.f;
#pragma unroll
            for (int n = 0; n < DS; n++) {
                float ee = __expf(dtv * A[n]);
                h[n] = ee * h[n] + w * sBC[s][n];
                ya += h[n] * sBC[s][DS + n];
            }
            float zv = zp[(size_t)s * 2 * DI];
            float sil = zv / (1.f + __expf(-zv));
            yp[(size_t)s * DI] = (ya + Dv * xv) * sil;
        }
    }
}

// ---------------- fused max-pool + classifier head ----------------
__global__ void poolhead_k(const float* __restrict__ h, const float* __restrict__ hw,
                           const float* __restrict__ hb, float* __restrict__ out)
{
    int n = blockIdx.x;        // 0..31
    int t = threadIdx.x;       // 0..383
    const float* base = h + (size_t)n * 196 * DM + t;
    float m = -1e30f;
    for (int p = 0; p < 196; p++) m = fmaxf(m, base[(size_t)p * DM]);
    __shared__ float sp[DM];
    sp[t] = m;
    __syncthreads();
    if (t < 96) {
        int c = t / 32, lane = t % 32;
        float acc = 0.f;
        for (int k = lane; k < DM; k += 32) acc += sp[k] * hw[c * DM + k];
#pragma unroll
        for (int o = 16; o; o >>= 1) acc += __shfl_xor_sync(0xffffffffu, acc, o);
        if (lane == 0) out[n * 3 + c] = acc + hb[c];
    }
}

// ---------------- host orchestration ----------------
static void mma_call(const float* A, int lda, const bf16* Wh, const bf16* Wl,
                     int N, int K, float* C, int ldc,
                     const float* bias, const float* res, int act, int nReal)
{
    dim3 grid(N / 64, NROW / 128);
    mma_gemm<<<grid, 256, MG_SMEM>>>(A, lda, Wh, Wl, K, C, ldc,
                                     bias, res, K, act, nReal);
}

extern "C" void kernel_launch(void* const* d_in, const int* in_sizes, int n_in,
                              void* d_out, int out_size)
{
    const float* x       = (const float*)d_in[0];
    const float* patch_w = (const float*)d_in[1];
    const float* patch_b = (const float*)d_in[2];
    const float* ln1_g   = (const float*)d_in[3];
    const float* ln1_b   = (const float*)d_in[4];
    const float* in_w    = (const float*)d_in[5];
    const float* conv_w  = (const float*)d_in[6];
    const float* conv_b  = (const float*)d_in[7];
    const float* xproj_w = (const float*)d_in[8];
    const float* dt_w    = (const float*)d_in[9];
    const float* dt_b    = (const float*)d_in[10];
    const float* A_log   = (const float*)d_in[11];
    const float* Dparam  = (const float*)d_in[12];
    const float* out_w   = (const float*)d_in[13];
    const float* ln2_g   = (const float*)d_in[14];
    const float* ln2_b   = (const float*)d_in[15];
    const float* fc1_w   = (const float*)d_in[16];
    const float* fc1_b   = (const float*)d_in[17];
    const float* fc2_w   = (const float*)d_in[18];
    const float* fc2_b   = (const float*)d_in[19];
    const float* head_w  = (const float*)d_in[20];
    const float* head_b  = (const float*)d_in[21];
    float* out = (float*)d_out;

    cudaFuncSetAttribute(mma_gemm, cudaFuncAttributeMaxDynamicSharedMemorySize, MG_SMEM);

    float *xf, *h, *ln, *xz, *xc, *dbl, *dt, *y, *m1, *P, *S, *h0;
    bf16 *wh, *wl;
    cudaGetSymbolAddress((void**)&xf,  g_xf);
    cudaGetSymbolAddress((void**)&h,   g_h);
    cudaGetSymbolAddress((void**)&ln,  g_ln);
    cudaGetSymbolAddress((void**)&xz,  g_xz);
    cudaGetSymbolAddress((void**)&xc,  g_xc);
    cudaGetSymbolAddress((void**)&dbl, g_dbl);
    cudaGetSymbolAddress((void**)&dt,  g_dt);
    cudaGetSymbolAddress((void**)&y,   g_y);
    cudaGetSymbolAddress((void**)&m1,  g_m1);
    cudaGetSymbolAddress((void**)&P,   g_P);
    cudaGetSymbolAddress((void**)&S,   g_S);
    cudaGetSymbolAddress((void**)&h0,  g_h0);
    cudaGetSymbolAddress((void**)&wh,  g_wh);
    cudaGetSymbolAddress((void**)&wl,  g_wl);

    // --- convert ALL weights in ONE launch ---
    wcvt_all_k<<<1184, 256>>>(patch_w, in_w, out_w, fc1_w, fc2_w, xproj_w, wh, wl);

    // patchify + patch embed -> h
    gather_patches_k<<<(NROW * DI / 4 + 255) / 256, 256>>>(x, xf);
    mma_call(xf, DI, wh + WOFF_PATCH, wl + WOFF_PATCH, DM, DI,
             h, DM, patch_b, nullptr, 0, DM);

    for (int i = 0; i < 4; i++) {
        const bf16* inwh = wh + WOFF_INW + (size_t)i * WSZ_INW;
        const bf16* inwl = wl + WOFF_INW + (size_t)i * WSZ_INW;
        const bf16* owh  = wh + WOFF_OUTW + (size_t)i * WSZ_OUTW;
        const bf16* owl  = wl + WOFF_OUTW + (size_t)i * WSZ_OUTW;
        const bf16* f1h  = wh + WOFF_FC1 + (size_t)i * WSZ_FC1;
        const bf16* f1l  = wl + WOFF_FC1 + (size_t)i * WSZ_FC1;
        const bf16* f2h  = wh + WOFF_FC2 + (size_t)i * WSZ_FC2;
        const bf16* f2l  = wl + WOFF_FC2 + (size_t)i * WSZ_FC2;
        const bf16* xph  = wh + WOFF_XPJ + (size_t)i * WSZ_XPJ;
        const bf16* xpl  = wl + WOFF_XPJ + (size_t)i * WSZ_XPJ;

        // --- mamba block ---
        layernorm_k<<<NROW, 128>>>(h, ln1_g + i * DM, ln1_b + i * DM, ln);
        mma_call(ln, DM, inwh, inwl, 2 * DI, DM,
                 xz, 2 * DI, nullptr, nullptr, 0, 2 * DI);
        conv_silu_k<<<(NROW * DI / 4 + 255) / 256, 256>>>(
            xz, conv_w + (size_t)i * DI * 4, conv_b + (size_t)i * DI, xc);
        // xproj on tensor cores (padded N=64, real 52)
        mma_call(xc, DI, xph, xpl, XPAD, DI,
                 dbl, XCOLS, nullptr, nullptr, 0, XCOLS);
        {
            dim3 grid((DI + TBN - 1) / TBN, NROW / TBM);
            sgemm128<<<grid, 256>>>(dbl, XCOLS, dt_w + (size_t)i * DI * DTR, DTR,
                                    dt, DI, dt_b + (size_t)i * DI, nullptr,
                                    DI, DTR, 1 /*softplus*/);
        }

        // --- chunked selective scan ---
        {
            dim3 gA(DI / 256, NC, BSZ);
            scan_chunk_partial<<<gA, 256>>>(dt, xc, dbl,
                                            A_log + (size_t)i * DI * DS, P, S);
            scan_chunk_seq<<<(BSZ * DI * DS + 255) / 256, 256>>>(P, S, h0);
            scan_chunk_final<<<gA, 256>>>(dt, xc, dbl, xz,
                                          A_log + (size_t)i * DI * DS,
                                          Dparam + (size_t)i * DI, h0, y);
        }

        mma_call(y, DI, owh, owl, DM, DI,
                 h, DM, nullptr, h /*residual*/, 0, DM);

        // --- mlp block ---
        layernorm_k<<<NROW, 128>>>(h, ln2_g + i * DM, ln2_b + i * DM, ln);
        mma_call(ln, DM, f1h, f1l, DHID, DM,
                 m1, DHID, fc1_b + (size_t)i * DHID, nullptr, 2 /*gelu*/, DHID);
        mma_call(m1, DHID, f2h, f2l, DM, DHID,
                 h, DM, fc2_b + (size_t)i * DM, h /*residual*/, 0, DM);
    }

    poolhead_k<<<32, DM>>>(h, head_w, head_b, out);
}

// round 17
// speedup vs baseline: 1.0762x; 1.0075x over previous
#include <cuda_runtime.h>
#include <cuda_bf16.h>
#include <cstdint>
#include <cstdio>

// ---------------- problem constants ----------------
#define BSZ    2
#define TT     16
#define LSEQ   3136          // TT * 196
#define NROW   6272          // BSZ * LSEQ (== 49*128)
#define DM     384
#define DI     768
#define DS     14
#define DTR    24
#define XCOLS  52            // DTR + 2*DS
#define XPAD   64            // xproj weight padded rows
#define DTPAD  32            // dt weight padded cols
#define DHID   1536          // 4*DM == 2*DI

// chunked scan
#define NC     56
#define CS     56

typedef __nv_bfloat16 bf16;

// weight arena offsets (elements)
#define WOFF_PATCH 0
#define WSZ_PATCH  (DM * DI)
#define WOFF_INW   (WOFF_PATCH + WSZ_PATCH)
#define WSZ_INW    (2 * DI * DM)
#define WOFF_OUTW  (WOFF_INW + 4 * WSZ_INW)
#define WSZ_OUTW   (DM * DI)
#define WOFF_FC1   (WOFF_OUTW + 4 * WSZ_OUTW)
#define WSZ_FC1    (DHID * DM)
#define WOFF_FC2   (WOFF_FC1 + 4 * WSZ_FC1)
#define WSZ_FC2    (DM * DHID)
#define WOFF_XPJ   (WOFF_FC2 + 4 * WSZ_FC2)
#define WSZ_XPJ    (XPAD * DI)                 // padded 64x768 per layer
#define WOFF_DTW   (WOFF_XPJ + 4 * WSZ_XPJ)
#define WSZ_DTW    (DI * DTPAD)                // padded 768x32 per layer
#define WARENA     (WOFF_DTW + 4 * WSZ_DTW)

// ---------------- scratch ----------------
__device__ float g_xf [NROW * DI];
__device__ float g_h  [NROW * DM];
__device__ float g_ln [NROW * DM];
__device__ float g_xz [NROW * 2 * DI];
__device__ float g_xc [NROW * DI];
__device__ float g_dbl[NROW * XCOLS];
__device__ float g_dt [NROW * DI];
__device__ float g_y  [NROW * DI];
__device__ float g_m1 [NROW * DHID];
__device__ float g_P  [BSZ * NC * DI * DS];
__device__ float g_S  [BSZ * NC * DI * DS];
__device__ float g_h0 [BSZ * NC * DI * DS];
// persistent hi/lo weight arena (all layers)
__device__ __align__(16) bf16 g_wh[WARENA];
__device__ __align__(16) bf16 g_wl[WARENA];

// ---------------- activations ----------------
__device__ __forceinline__ float softplus_f(float x) {
    return fmaxf(x, 0.f) + log1pf(expf(-fabsf(x)));
}
__device__ __forceinline__ float gelu_f(float x) {
    float x3 = x * x * x;
    float t = tanhf(0.7978845608028654f * (x + 0.044715f * x3));
    return 0.5f * x * (1.f + t);
}

__device__ __forceinline__ uint32_t smem_u32(const void* p) {
    uint32_t a;
    asm("{ .reg .u64 t; cvta.to.shared.u64 t, %1; cvt.u32.u64 %0, t; }" : "=r"(a) : "l"(p));
    return a;
}

__device__ __forceinline__ void split_bf16(float v, bf16& hi, bf16& lo) {
    hi = __float2bfloat16(v);
    lo = __float2bfloat16(v - __bfloat162float(hi));
}

// ================= bf16-split tensor-core GEMM (mma.sync) =================
// C[M,N] = act(A[M,K]*W^T + bias) + res.  A fp32 (split in-kernel);
// W pre-split bf16 hi/lo from the arena.  M%128==0, N%64==0, K%32==0.
// Warp tile 32x32 (8 warps as 4x2).
#define KB 32
#define SROW 40
#define MG_AH 0
#define MG_AL 10240
#define MG_WH 20480
#define MG_WL 25600
#define MG_STAGE 30720
#define MG_SMEM (2 * MG_STAGE)

__device__ __forceinline__ void ldm_x4(uint32_t& r0, uint32_t& r1, uint32_t& r2,
                                       uint32_t& r3, uint32_t addr) {
    asm volatile("ldmatrix.sync.aligned.m8n8.x4.shared.b16 {%0,%1,%2,%3}, [%4];"
                 : "=r"(r0), "=r"(r1), "=r"(r2), "=r"(r3) : "r"(addr));
}
__device__ __forceinline__ void mma_bf16(float* d, const uint32_t* a,
                                         uint32_t b0, uint32_t b1) {
    asm volatile(
        "mma.sync.aligned.m16n8k16.row.col.f32.bf16.bf16.f32 "
        "{%0,%1,%2,%3}, {%4,%5,%6,%7}, {%8,%9}, {%0,%1,%2,%3};"
        : "+f"(d[0]), "+f"(d[1]), "+f"(d[2]), "+f"(d[3])
        : "r"(a[0]), "r"(a[1]), "r"(a[2]), "r"(a[3]), "r"(b0), "r"(b1));
}

__device__ __forceinline__ void cvt_split4(float4 v, uint16_t* hi, uint16_t* lo) {
    __nv_bfloat16 hx = __float2bfloat16(v.x), hy = __float2bfloat16(v.y);
    __nv_bfloat16 hz = __float2bfloat16(v.z), hw = __float2bfloat16(v.w);
    __nv_bfloat16 gx = __float2bfloat16(v.x - __bfloat162float(hx));
    __nv_bfloat16 gy = __float2bfloat16(v.y - __bfloat162float(hy));
    __nv_bfloat16 gz = __float2bfloat16(v.z - __bfloat162float(hz));
    __nv_bfloat16 gw = __float2bfloat16(v.w - __bfloat162float(hw));
    uint2 hp, lp;
    hp.x = (uint32_t)__bfloat16_as_ushort(hy) << 16 | __bfloat16_as_ushort(hx);
    hp.y = (uint32_t)__bfloat16_as_ushort(hw) << 16 | __bfloat16_as_ushort(hz);
    lp.x = (uint32_t)__bfloat16_as_ushort(gy) << 16 | __bfloat16_as_ushort(gx);
    lp.y = (uint32_t)__bfloat16_as_ushort(gw) << 16 | __bfloat16_as_ushort(gz);
    *(uint2*)hi = hp;
    *(uint2*)lo = lp;
}

__global__ __launch_bounds__(256, 2) void mma_gemm(
    const float* __restrict__ A, int lda,
    const bf16* __restrict__ Wh, const bf16* __restrict__ Wl, int ldw,
    float* __restrict__ C, int ldc,
    const float* __restrict__ bias,
    const float* __restrict__ res,
    int K, int act, int nReal)
{
    extern __shared__ __align__(16) char dsm[];

    int tid  = threadIdx.x;
    int wid  = tid >> 5;
    int lane = tid & 31;
    int bm0 = blockIdx.y * 128;
    int bn0 = blockIdx.x * 64;
    int wm = (wid >> 1) * 32;   // 0/32/64/96
    int wn = (wid & 1) * 32;    // 0/32

    float acc[2][4][4];
#pragma unroll
    for (int mt = 0; mt < 2; mt++)
#pragma unroll
        for (int nt = 0; nt < 4; nt++)
#pragma unroll
            for (int i = 0; i < 4; i++) acc[mt][nt][i] = 0.f;

    int lrA[4], lcA[4];
#pragma unroll
    for (int i = 0; i < 4; i++) {
        int idx = i * 256 + tid;
        lrA[i] = idx >> 3;
        lcA[i] = (idx & 7) * 4;
    }
    int wr = tid >> 2, wc = (tid & 3) * 8;
    uint32_t oW = (uint32_t)(wr * SROW + wc) * 2;

    const bf16* gWh = Wh + (size_t)(bn0 + wr) * ldw + wc;
    const bf16* gWl = Wl + (size_t)(bn0 + wr) * ldw + wc;

    float4 pa[4];
    uint4 pwh, pwl;
#pragma unroll
    for (int i = 0; i < 4; i++)
        pa[i] = *(const float4*)(A + (size_t)(bm0 + lrA[i]) * lda + lcA[i]);
    pwh = *(const uint4*)gWh;
    pwl = *(const uint4*)gWl;

    {
        char* sn = dsm;
#pragma unroll
        for (int i = 0; i < 4; i++) {
            int o = lrA[i] * SROW + lcA[i];
            cvt_split4(pa[i], (uint16_t*)(sn + MG_AH) + o, (uint16_t*)(sn + MG_AL) + o);
        }
        *(uint4*)(sn + MG_WH + oW) = pwh;
        *(uint4*)(sn + MG_WL + oW) = pwl;
    }
    __syncthreads();

    uint32_t sAh[2], sAl[2], sWh[2], sWl[2];
#pragma unroll
    for (int s = 0; s < 2; s++) {
        sAh[s] = smem_u32(dsm + s * MG_STAGE + MG_AH);
        sAl[s] = smem_u32(dsm + s * MG_STAGE + MG_AL);
        sWh[s] = smem_u32(dsm + s * MG_STAGE + MG_WH);
        sWl[s] = smem_u32(dsm + s * MG_STAGE + MG_WL);
    }

    int frow = lane & 15;
    int fk   = (lane >> 4) << 3;

    int nch = K / KB;
    for (int c = 0; c < nch; c++) {
        int cur = c & 1, nxt = cur ^ 1;

        if (c + 1 < nch) {
            int ko = (c + 1) * KB;
#pragma unroll
            for (int i = 0; i < 4; i++)
                pa[i] = *(const float4*)(A + (size_t)(bm0 + lrA[i]) * lda + ko + lcA[i]);
            pwh = *(const uint4*)(gWh + ko);
            pwl = *(const uint4*)(gWl + ko);
        }

#pragma unroll
        for (int k0 = 0; k0 < KB; k0 += 16) {
            // W fragments: 32 cols of this warp, hi and lo (4 ldmatrix)
            uint32_t bh[4][2], bl[4][2];
#pragma unroll
            for (int nh = 0; nh < 2; nh++) {
                uint32_t off = (uint32_t)((wn + nh * 16 + frow) * SROW + k0 + fk) * 2;
                uint32_t r0, r1, r2, r3;
                ldm_x4(r0, r1, r2, r3, sWh[cur] + off);
                bh[nh * 2 + 0][0] = r0; bh[nh * 2 + 0][1] = r2;
                bh[nh * 2 + 1][0] = r1; bh[nh * 2 + 1][1] = r3;
                ldm_x4(r0, r1, r2, r3, sWl[cur] + off);
                bl[nh * 2 + 0][0] = r0; bl[nh * 2 + 0][1] = r2;
                bl[nh * 2 + 1][0] = r1; bl[nh * 2 + 1][1] = r3;
            }
            // A fragments: 32 rows, hi and lo (4 ldmatrix), then 24 MMA
#pragma unroll
            for (int mt = 0; mt < 2; mt++) {
                uint32_t off = (uint32_t)((wm + mt * 16 + frow) * SROW + k0 + fk) * 2;
                uint32_t ah[4], al[4];
                ldm_x4(ah[0], ah[1], ah[2], ah[3], sAh[cur] + off);
                ldm_x4(al[0], al[1], al[2], al[3], sAl[cur] + off);
#pragma unroll
                for (int nt = 0; nt < 4; nt++) {
                    mma_bf16(acc[mt][nt], ah, bh[nt][0], bh[nt][1]);
                    mma_bf16(acc[mt][nt], ah, bl[nt][0], bl[nt][1]);
                    mma_bf16(acc[mt][nt], al, bh[nt][0], bh[nt][1]);
                }
            }
        }

        if (c + 1 < nch) {
            char* sn = dsm + nxt * MG_STAGE;
#pragma unroll
            for (int i = 0; i < 4; i++) {
                int o = lrA[i] * SROW + lcA[i];
                cvt_split4(pa[i], (uint16_t*)(sn + MG_AH) + o, (uint16_t*)(sn + MG_AL) + o);
            }
            *(uint4*)(sn + MG_WH + oW) = pwh;
            *(uint4*)(sn + MG_WL + oW) = pwl;
            __syncthreads();
        }
    }

    // epilogue: fragment row = lane/4 (+8), col = (lane%4)*2 (+1)
    int gq = lane >> 2;
    int gr = (lane & 3) * 2;
#pragma unroll
    for (int mt = 0; mt < 2; mt++) {
#pragma unroll
        for (int half = 0; half < 2; half++) {
            int gm = bm0 + wm + mt * 16 + gq + half * 8;
            float* crow = C + (size_t)gm * ldc;
            const float* rrow = res ? res + (size_t)gm * ldc : nullptr;
#pragma unroll
            for (int nt = 0; nt < 4; nt++) {
                int gn = bn0 + wn + nt * 8 + gr;
                if (gn >= nReal) continue;
                float v0 = acc[mt][nt][half * 2 + 0];
                float v1 = acc[mt][nt][half * 2 + 1];
                if (bias) { v0 += bias[gn]; v1 += bias[gn + 1]; }
                if (act == 2)      { v0 = gelu_f(v0);     v1 = gelu_f(v1); }
                else if (act == 1) { v0 = softplus_f(v0); v1 = softplus_f(v1); }
                if (rrow) { v0 += rrow[gn]; v1 += rrow[gn + 1]; }
                *(float2*)(crow + gn) = make_float2(v0, v1);
            }
        }
    }
}

// ---------------- ALL weights fp32 -> bf16 hi/lo in ONE launch ----------------
__global__ void wcvt_all_k(const float* __restrict__ patch_w,
                           const float* __restrict__ in_w,
                           const float* __restrict__ out_w,
                           const float* __restrict__ fc1_w,
                           const float* __restrict__ fc2_w,
                           const float* __restrict__ xproj_w,
                           const float* __restrict__ dt_w,
                           bf16* __restrict__ hi, bf16* __restrict__ lo)
{
    for (int i = blockIdx.x * 256 + threadIdx.x; i < WARENA; i += gridDim.x * 256) {
        float v;
        if (i < WOFF_INW) {
            v = patch_w[i - WOFF_PATCH];
        } else if (i < WOFF_OUTW) {
            v = in_w[i - WOFF_INW];
        } else if (i < WOFF_FC1) {
            v = out_w[i - WOFF_OUTW];
        } else if (i < WOFF_FC2) {
            v = fc1_w[i - WOFF_FC1];
        } else if (i < WOFF_XPJ) {
            v = fc2_w[i - WOFF_FC2];
        } else if (i < WOFF_DTW) {
            int rem   = i - WOFF_XPJ;
            int layer = rem / (XPAD * DI);
            int r2    = rem % (XPAD * DI);
            int row   = r2 / DI;
            int col   = r2 % DI;
            v = (row < XCOLS) ? xproj_w[((size_t)layer * XCOLS + row) * DI + col] : 0.f;
        } else {
            int rem   = i - WOFF_DTW;
            int layer = rem / (DI * DTPAD);
            int r2    = rem % (DI * DTPAD);
            int row   = r2 / DTPAD;
            int col   = r2 % DTPAD;
            v = (col < DTR) ? dt_w[((size_t)layer * DI + row) * DTR + col] : 0.f;
        }
        bf16 h, l;
        split_bf16(v, h, l);
        hi[i] = h; lo[i] = l;
    }
}

// ---------------- patchify gather (float4 vectorized) ----------------
__global__ void gather_patches_k(const float* __restrict__ x, float* __restrict__ xf) {
    int idx = blockIdx.x * blockDim.x + threadIdx.x;
    if (idx >= NROW * DI / 4) return;
    int c4  = (idx % (DI / 4)) * 4;
    int row = idx / (DI / 4);
    int n  = row / 196, p = row % 196;
    int ph = p / 14,   pw = p % 14;
    int ch = c4 >> 8;
    int rem = c4 & 255;
    int py = rem >> 4, px = rem & 15;
    float4 v = *(const float4*)(x + ((size_t)(n * 3 + ch) * 224 + (ph * 16 + py)) * 224
                                + (pw * 16 + px));
    *(float4*)(xf + (size_t)row * DI + c4) = v;
}

// ---------------- layernorm ----------------
__global__ void layernorm_k(const float* __restrict__ x, const float* __restrict__ g,
                            const float* __restrict__ b, float* __restrict__ out)
{
    int row = blockIdx.x;
    int t = threadIdx.x;
    const float* xr = x + (size_t)row * DM;
    float v0 = xr[t], v1 = xr[t + 128], v2 = xr[t + 256];
    float s  = v0 + v1 + v2;
    float s2 = v0 * v0 + v1 * v1 + v2 * v2;
#pragma unroll
    for (int o = 16; o; o >>= 1) {
        s  += __shfl_xor_sync(0xffffffffu, s,  o);
        s2 += __shfl_xor_sync(0xffffffffu, s2, o);
    }
    __shared__ float ss[4], ss2[4];
    int w = t >> 5;
    if ((t & 31) == 0) { ss[w] = s; ss2[w] = s2; }
    __syncthreads();
    s  = ss[0] + ss[1] + ss[2] + ss[3];
    s2 = ss2[0] + ss2[1] + ss2[2] + ss2[3];
    float mu  = s * (1.f / DM);
    float var = s2 * (1.f / DM) - mu * mu;
    float r = rsqrtf(var + 1e-5f);
    float* orow = out + (size_t)row * DM;
    orow[t]       = (v0 - mu) * r * g[t]       + b[t];
    orow[t + 128] = (v1 - mu) * r * g[t + 128] + b[t + 128];
    orow[t + 256] = (v2 - mu) * r * g[t + 256] + b[t + 256];
}

// ---------------- causal conv1d (width 4) + silu, vectorized ----------------
__global__ void conv_silu_k(const float* __restrict__ xz, const float* __restrict__ cw,
                            const float* __restrict__ cb, float* __restrict__ xc)
{
    int idx = blockIdx.x * blockDim.x + threadIdx.x;
    if (idx >= NROW * DI / 4) return;
    int e4 = (idx % (DI / 4)) * 4;
    int bl = idx / (DI / 4);
    int b = bl / LSEQ, l = bl % LSEQ;

    float4 w0 = *(const float4*)(cw + (e4 + 0) * 4);
    float4 w1 = *(const float4*)(cw + (e4 + 1) * 4);
    float4 w2 = *(const float4*)(cw + (e4 + 2) * 4);
    float4 w3 = *(const float4*)(cw + (e4 + 3) * 4);

    float4 xv[4];
#pragma unroll
    for (int k = 0; k < 4; k++) {
        int ll = l + k - 3;
        xv[k] = (ll >= 0)
            ? *(const float4*)(xz + ((size_t)b * LSEQ + ll) * (2 * DI) + e4)
            : make_float4(0.f, 0.f, 0.f, 0.f);
    }

    float4 acc = *(const float4*)(cb + e4);
    acc.x += w0.x * xv[0].x + w0.y * xv[1].x + w0.z * xv[2].x + w0.w * xv[3].x;
    acc.y += w1.x * xv[0].y + w1.y * xv[1].y + w1.z * xv[2].y + w1.w * xv[3].y;
    acc.z += w2.x * xv[0].z + w2.y * xv[1].z + w2.z * xv[2].z + w2.w * xv[3].z;
    acc.w += w3.x * xv[0].w + w3.y * xv[1].w + w3.z * xv[2].w + w3.w * xv[3].w;

    acc.x = acc.x / (1.f + __expf(-acc.x));
    acc.y = acc.y / (1.f + __expf(-acc.y));
    acc.z = acc.z / (1.f + __expf(-acc.z));
    acc.w = acc.w / (1.f + __expf(-acc.w));
    *(float4*)(xc + (size_t)bl * DI + e4) = acc;
}

// ================= chunked selective scan =================
__device__ __forceinline__ bool load_A(const float* __restrict__ A_log, int d, float* A) {
    bool structured = true;
#pragma unroll
    for (int n = 0; n < DS; n++) A[n] = -__expf(A_log[d * DS + n]);
#pragma unroll
    for (int n = 1; n < DS; n++) {
        float want = (n + 1) * A[0];
        structured &= fabsf(A[n] - want) <= 1e-4f * fabsf(want);
    }
    return structured;
}

// pass A: per-chunk (P, S). P via closed form exp(A[n]*sum_dt).
__global__ __launch_bounds__(256) void scan_chunk_partial(
    const float* __restrict__ dt, const float* __restrict__ xc,
    const float* __restrict__ dbl, const float* __restrict__ A_log,
    float* __restrict__ Pout, float* __restrict__ Sout)
{
    __shared__ float sB[CS][DS];
    int d = blockIdx.x * 256 + threadIdx.x;
    int c = blockIdx.y;
    int b = blockIdx.z;
    int l0 = c * CS;

    for (int i = threadIdx.x; i < CS * DS; i += 256) {
        int s = i / DS, j = i % DS;
        sB[s][j] = dbl[((size_t)(b * LSEQ + l0 + s)) * XCOLS + DTR + j];
    }
    __syncthreads();

    float A[DS];
    bool structured = load_A(A_log, d, A);
    float A0 = A[0];

    float S[DS];
#pragma unroll
    for (int n = 0; n < DS; n++) S[n] = 0.f;
    float dtsum = 0.f;

    const float* dtp = dt + (size_t)(b * LSEQ + l0) * DI + d;
    const float* xcp = xc + (size_t)(b * LSEQ + l0) * DI + d;

    if (structured) {
        for (int s = 0; s < CS; s++) {
            float dtv = dtp[(size_t)s * DI];
            float xv  = xcp[(size_t)s * DI];
            float w = dtv * xv;
            dtsum += dtv;
            float e1 = __expf(dtv * A0);
            float ee = 1.f;
#pragma unroll
            for (int n = 0; n < DS; n++) {
                ee *= e1;
                S[n] = ee * S[n] + w * sB[s][n];
            }
        }
    } else {
        for (int s = 0; s < CS; s++) {
            float dtv = dtp[(size_t)s * DI];
            float xv  = xcp[(size_t)s * DI];
            float w = dtv * xv;
            dtsum += dtv;
#pragma unroll
            for (int n = 0; n < DS; n++) {
                float ee = __expf(dtv * A[n]);
                S[n] = ee * S[n] + w * sB[s][n];
            }
        }
    }

    size_t base = ((size_t)(b * NC + c) * DI + d) * DS;
    if (structured) {
        float e1s = __expf(A0 * dtsum);
        float pp = 1.f;
#pragma unroll
        for (int n = 0; n < DS; n++) {
            pp *= e1s;
            Pout[base + n] = pp;
            Sout[base + n] = S[n];
        }
    } else {
#pragma unroll
        for (int n = 0; n < DS; n++) {
            Pout[base + n] = __expf(A[n] * dtsum);
            Sout[base + n] = S[n];
        }
    }
}

__global__ __launch_bounds__(256) void scan_chunk_seq(
    const float* __restrict__ P, const float* __restrict__ S, float* __restrict__ h0)
{
    int idx = blockIdx.x * blockDim.x + threadIdx.x;
    if (idx >= BSZ * DI * DS) return;
    int b = idx / (DI * DS);
    int r = idx % (DI * DS);
    float h = 0.f;
    for (int c = 0; c < NC; c++) {
        size_t off = (size_t)b * NC * DI * DS + (size_t)c * DI * DS + r;
        h0[off] = h;
        h = P[off] * h + S[off];
    }
}

__global__ __launch_bounds__(256) void scan_chunk_final(
    const float* __restrict__ dt, const float* __restrict__ xc,
    const float* __restrict__ dbl, const float* __restrict__ xz,
    const float* __restrict__ A_log, const float* __restrict__ Dp,
    const float* __restrict__ h0, float* __restrict__ y)
{
    __shared__ float sBC[CS][2 * DS];
    int d = blockIdx.x * 256 + threadIdx.x;
    int c = blockIdx.y;
    int b = blockIdx.z;
    int l0 = c * CS;

    for (int i = threadIdx.x; i < CS * 2 * DS; i += 256) {
        int s = i / (2 * DS), j = i % (2 * DS);
        sBC[s][j] = dbl[((size_t)(b * LSEQ + l0 + s)) * XCOLS + DTR + j];
    }
    __syncthreads();

    float A[DS];
    bool structured = load_A(A_log, d, A);
    float A0 = A[0];
    float Dv = Dp[d];

    float h[DS];
    size_t hbase = ((size_t)(b * NC + c) * DI + d) * DS;
#pragma unroll
    for (int n = 0; n < DS; n++) h[n] = h0[hbase + n];

    const float* dtp = dt + (size_t)(b * LSEQ + l0) * DI + d;
    const float* xcp = xc + (size_t)(b * LSEQ + l0) * DI + d;
    const float* zp  = xz + (size_t)(b * LSEQ + l0) * 2 * DI + DI + d;
    float* yp = y + (size_t)(b * LSEQ + l0) * DI + d;

    if (structured) {
        for (int s = 0; s < CS; s++) {
            float dtv = dtp[(size_t)s * DI];
            float xv  = xcp[(size_t)s * DI];
            float w = dtv * xv;
            float e1 = __expf(dtv * A0);
            float ee = 1.f;
            float ya = 0.f;
#pragma unroll
            for (int n = 0; n < DS; n++) {
                ee *= e1;
                h[n] = ee * h[n] + w * sBC[s][n];
                ya += h[n] * sBC[s][DS + n];
            }
            float zv = zp[(size_t)s * 2 * DI];
            float sil = zv / (1.f + __expf(-zv));
            yp[(size_t)s * DI] = (ya + Dv * xv) * sil;
        }
    } else {
        for (int s = 0; s < CS; s++) {
            float dtv = dtp[(size_t)s * DI];
            float xv  = xcp[(size_t)s * DI];
            float w = dtv * xv;
            float ya = 0.f;
#pragma unroll
            for (int n = 0; n < DS; n++) {
                float ee = __expf(dtv * A[n]);
                h[n] = ee * h[n] + w * sBC[s][n];
                ya += h[n] * sBC[s][DS + n];
            }
            float zv = zp[(size_t)s * 2 * DI];
            float sil = zv / (1.f + __expf(-zv));
            yp[(size_t)s * DI] = (ya + Dv * xv) * sil;
        }
    }
}

// ---------------- fused max-pool + classifier head ----------------
__global__ void poolhead_k(const float* __restrict__ h, const float* __restrict__ hw,
                           const float* __restrict__ hb, float* __restrict__ out)
{
    int n = blockIdx.x;        // 0..31
    int t = threadIdx.x;       // 0..383
    const float* base = h + (size_t)n * 196 * DM + t;
    float m = -1e30f;
    for (int p = 0; p < 196; p++) m = fmaxf(m, base[(size_t)p * DM]);
    __shared__ float sp[DM];
    sp[t] = m;
    __syncthreads();
    if (t < 96) {
        int c = t / 32, lane = t % 32;
        float acc = 0.f;
        for (int k = lane; k < DM; k += 32) acc += sp[k] * hw[c * DM + k];
#pragma unroll
        for (int o = 16; o; o >>= 1) acc += __shfl_xor_sync(0xffffffffu, acc, o);
        if (lane == 0) out[n * 3 + c] = acc + hb[c];
    }
}

// ---------------- host orchestration ----------------
static void mma_call(const float* A, int lda, const bf16* Wh, const bf16* Wl,
                     int N, int K, float* C, int ldc,
                     const float* bias, const float* res, int act, int nReal)
{
    dim3 grid(N / 64, NROW / 128);
    mma_gemm<<<grid, 256, MG_SMEM>>>(A, lda, Wh, Wl, K, C, ldc,
                                     bias, res, K, act, nReal);
}

extern "C" void kernel_launch(void* const* d_in, const int* in_sizes, int n_in,
                              void* d_out, int out_size)
{
    const float* x       = (const float*)d_in[0];
    const float* patch_w = (const float*)d_in[1];
    const float* patch_b = (const float*)d_in[2];
    const float* ln1_g   = (const float*)d_in[3];
    const float* ln1_b   = (const float*)d_in[4];
    const float* in_w    = (const float*)d_in[5];
    const float* conv_w  = (const float*)d_in[6];
    const float* conv_b  = (const float*)d_in[7];
    const float* xproj_w = (const float*)d_in[8];
    const float* dt_w    = (const float*)d_in[9];
    const float* dt_b    = (const float*)d_in[10];
    const float* A_log   = (const float*)d_in[11];
    const float* Dparam  = (const float*)d_in[12];
    const float* out_w   = (const float*)d_in[13];
    const float* ln2_g   = (const float*)d_in[14];
    const float* ln2_b   = (const float*)d_in[15];
    const float* fc1_w   = (const float*)d_in[16];
    const float* fc1_b   = (const float*)d_in[17];
    const float* fc2_w   = (const float*)d_in[18];
    const float* fc2_b   = (const float*)d_in[19];
    const float* head_w  = (const float*)d_in[20];
    const float* head_b  = (const float*)d_in[21];
    float* out = (float*)d_out;

    cudaFuncSetAttribute(mma_gemm, cudaFuncAttributeMaxDynamicSharedMemorySize, MG_SMEM);

    float *xf, *h, *ln, *xz, *xc, *dbl, *dt, *y, *m1, *P, *S, *h0;
    bf16 *wh, *wl;
    cudaGetSymbolAddress((void**)&xf,  g_xf);
    cudaGetSymbolAddress((void**)&h,   g_h);
    cudaGetSymbolAddress((void**)&ln,  g_ln);
    cudaGetSymbolAddress((void**)&xz,  g_xz);
    cudaGetSymbolAddress((void**)&xc,  g_xc);
    cudaGetSymbolAddress((void**)&dbl, g_dbl);
    cudaGetSymbolAddress((void**)&dt,  g_dt);
    cudaGetSymbolAddress((void**)&y,   g_y);
    cudaGetSymbolAddress((void**)&m1,  g_m1);
    cudaGetSymbolAddress((void**)&P,   g_P);
    cudaGetSymbolAddress((void**)&S,   g_S);
    cudaGetSymbolAddress((void**)&h0,  g_h0);
    cudaGetSymbolAddress((void**)&wh,  g_wh);
    cudaGetSymbolAddress((void**)&wl,  g_wl);

    // --- convert ALL weights in ONE launch ---
    wcvt_all_k<<<1184, 256>>>(patch_w, in_w, out_w, fc1_w, fc2_w, xproj_w, dt_w, wh, wl);

    // patchify + patch embed -> h
    gather_patches_k<<<(NROW * DI / 4 + 255) / 256, 256>>>(x, xf);
    mma_call(xf, DI, wh + WOFF_PATCH, wl + WOFF_PATCH, DM, DI,
             h, DM, patch_b, nullptr, 0, DM);

    for (int i = 0; i < 4; i++) {
        const bf16* inwh = wh + WOFF_INW + (size_t)i * WSZ_INW;
        const bf16* inwl = wl + WOFF_INW + (size_t)i * WSZ_INW;
        const bf16* owh  = wh + WOFF_OUTW + (size_t)i * WSZ_OUTW;
        const bf16* owl  = wl + WOFF_OUTW + (size_t)i * WSZ_OUTW;
        const bf16* f1h  = wh + WOFF_FC1 + (size_t)i * WSZ_FC1;
        const bf16* f1l  = wl + WOFF_FC1 + (size_t)i * WSZ_FC1;
        const bf16* f2h  = wh + WOFF_FC2 + (size_t)i * WSZ_FC2;
        const bf16* f2l  = wl + WOFF_FC2 + (size_t)i * WSZ_FC2;
        const bf16* xph  = wh + WOFF_XPJ + (size_t)i * WSZ_XPJ;
        const bf16* xpl  = wl + WOFF_XPJ + (size_t)i * WSZ_XPJ;
        const bf16* dth  = wh + WOFF_DTW + (size_t)i * WSZ_DTW;
        const bf16* dtl  = wl + WOFF_DTW + (size_t)i * WSZ_DTW;

        // --- mamba block ---
        layernorm_k<<<NROW, 128>>>(h, ln1_g + i * DM, ln1_b + i * DM, ln);
        mma_call(ln, DM, inwh, inwl, 2 * DI, DM,
                 xz, 2 * DI, nullptr, nullptr, 0, 2 * DI);
        conv_silu_k<<<(NROW * DI / 4 + 255) / 256, 256>>>(
            xz, conv_w + (size_t)i * DI * 4, conv_b + (size_t)i * DI, xc);
        // xproj on tensor cores (padded N=64, real 52)
        mma_call(xc, DI, xph, xpl, XPAD, DI,
                 dbl, XCOLS, nullptr, nullptr, 0, XCOLS);
        // dt on tensor cores (padded K=32; A=dbl lda=52)
        mma_call(dbl, XCOLS, dth, dtl, DI, DTPAD,
                 dt, DI, dt_b + (size_t)i * DI, nullptr, 1 /*softplus*/, DI);

        // --- chunked selective scan ---
        {
            dim3 gA(DI / 256, NC, BSZ);
            scan_chunk_partial<<<gA, 256>>>(dt, xc, dbl,
                                            A_log + (size_t)i * DI * DS, P, S);
            scan_chunk_seq<<<(BSZ * DI * DS + 255) / 256, 256>>>(P, S, h0);
            scan_chunk_final<<<gA, 256>>>(dt, xc, dbl, xz,
                                          A_log + (size_t)i * DI * DS,
                                          Dparam + (size_t)i * DI, h0, y);
        }

        mma_call(y, DI, owh, owl, DM, DI,
                 h, DM, nullptr, h /*residual*/, 0, DM);

        // --- mlp block ---
        layernorm_k<<<NROW, 128>>>(h, ln2_g + i * DM, ln2_b + i * DM, ln);
        mma_call(ln, DM, f1h, f1l, DHID, DM,
                 m1, DHID, fc1_b + (size_t)i * DHID, nullptr, 2 /*gelu*/, DHID);
        mma_call(m1, DHID, f2h, f2l, DM, DHID,
                 h, DM, fc2_b + (size_t)i * DM, h /*residual*/, 0, DM);
    }

    poolhead_k<<<32, DM>>>(h, head_w, head_b, out);
}